// round 2
// baseline (speedup 1.0000x reference)
#include <cuda_runtime.h>
#include <cuda_bf16.h>
#include <math.h>

// ---------------- problem constants ----------------
#define NB 5
#define SEQ 1024
#define T 1025
#define DM 512
#define NHEAD 8
#define HD 64
#define DFF 2048
#define NL 4
#define NTOK 51
#define MLPD 256
#define CLASSES 7
#define GH 3
#define GHID 64
#define GCLS 5
#define MROWS (NB * T)
#define GAT_GRAPHS (SEQ * 5)
#define OUT_GAT_BASE (NB * CLASSES)

// XOR swizzle: permutes groups-of-4 within a 64-wide row based on row index
#define SW(i, r) ((i) ^ ((((r) >> 2) & 7) << 2))

// ---------------- scratch ----------------
__device__ float g_h [MROWS * DM];
__device__ float g_q [MROWS * DM];
__device__ float g_k [MROWS * DM];
__device__ float g_v [MROWS * DM];
__device__ float g_ao[MROWS * DM];
__device__ float g_t [MROWS * DM];
__device__ float g_ff[MROWS * DFF];

// ---------------- encoder ----------------
__global__ void enc_kernel(const float* __restrict__ x,
                           const float* __restrict__ W_enc,
                           const float* __restrict__ b_enc,
                           const float* __restrict__ cls_tok,
                           const float* __restrict__ pos_emb,
                           float* __restrict__ h)
{
    int row = blockIdx.x;
    int b = row / T, t = row % T;
    int tid = threadIdx.x;           // 128
    float* hr = h + (size_t)row * DM;
    if (t == 0) {
        for (int d = tid; d < DM; d += 128)
            hr[d] = cls_tok[d] + pos_emb[d];
        return;
    }
    __shared__ float xs[NTOK];
    if (tid < NTOK) xs[tid] = x[(size_t)b * SEQ * NTOK + (size_t)(t - 1) * NTOK + tid];
    __syncthreads();
    for (int d = tid; d < DM; d += 128) {
        float acc = b_enc[d] + pos_emb[(size_t)t * DM + d];
        #pragma unroll 17
        for (int kk = 0; kk < NTOK; kk++)
            acc += xs[kk] * W_enc[kk * DM + d];
        hr[d] = acc;
    }
}

// ---------------- GEMM: 128x128x16 tiles, 8x8 microtile ----------------
__global__ __launch_bounds__(256, 2) void gemm_kernel(
    const float* __restrict__ A, const float* __restrict__ B,
    const float* __restrict__ bias, float* __restrict__ C,
    int M, int N, int K, int relu)
{
    __shared__ float As[16][128];   // transposed A tile
    __shared__ float Bs[16][128];
    int tid = threadIdx.x;
    int ty = tid >> 4, tx = tid & 15;
    int bm = blockIdx.y * 128;
    int bn = blockIdx.x * 128;

    int ar = tid >> 2;               // 0..63 (two row groups)
    int ac = (tid & 3) << 2;         // k offset 0,4,8,12
    int br = tid >> 4;               // 0..15
    int bc = (tid & 15) << 2;        // 0..60 (two col groups)

    float acc[8][8];
    #pragma unroll
    for (int i = 0; i < 8; i++)
        #pragma unroll
        for (int j = 0; j < 8; j++) acc[i][j] = 0.f;

    for (int k0 = 0; k0 < K; k0 += 16) {
        #pragma unroll
        for (int g = 0; g < 2; g++) {
            int m = bm + ar + g * 64;
            float4 av = make_float4(0.f, 0.f, 0.f, 0.f);
            if (m < M) av = *(const float4*)(A + (size_t)m * K + k0 + ac);
            As[ac + 0][ar + g * 64] = av.x;
            As[ac + 1][ar + g * 64] = av.y;
            As[ac + 2][ar + g * 64] = av.z;
            As[ac + 3][ar + g * 64] = av.w;
        }
        #pragma unroll
        for (int g = 0; g < 2; g++) {
            float4 bv = *(const float4*)(B + (size_t)(k0 + br) * N + bn + bc + g * 64);
            *(float4*)&Bs[br][bc + g * 64] = bv;
        }
        __syncthreads();
        #pragma unroll
        for (int k = 0; k < 16; k++) {
            float a[8], b[8];
            *(float4*)&a[0] = *(float4*)&As[k][ty << 3];
            *(float4*)&a[4] = *(float4*)&As[k][(ty << 3) + 4];
            *(float4*)&b[0] = *(float4*)&Bs[k][tx << 3];
            *(float4*)&b[4] = *(float4*)&Bs[k][(tx << 3) + 4];
            #pragma unroll
            for (int i = 0; i < 8; i++)
                #pragma unroll
                for (int j = 0; j < 8; j++)
                    acc[i][j] += a[i] * b[j];
        }
        __syncthreads();
    }

    #pragma unroll
    for (int ii = 0; ii < 8; ii++) {
        int row = bm + (ty << 3) + ii;
        if (row >= M) continue;
        #pragma unroll
        for (int g = 0; g < 2; g++) {
            int col = bn + (tx << 3) + g * 4;
            float4 bb = *(const float4*)(bias + col);
            float4 r;
            r.x = acc[ii][g * 4 + 0] + bb.x;
            r.y = acc[ii][g * 4 + 1] + bb.y;
            r.z = acc[ii][g * 4 + 2] + bb.z;
            r.w = acc[ii][g * 4 + 3] + bb.w;
            if (relu) {
                r.x = fmaxf(r.x, 0.f); r.y = fmaxf(r.y, 0.f);
                r.z = fmaxf(r.z, 0.f); r.w = fmaxf(r.w, 0.f);
            }
            *(float4*)(C + (size_t)row * N + col) = r;
        }
    }
}

// ---------------- flash attention: 64q x 64k tiles, 8x4 microtile, 128 thr ----------------
__global__ __launch_bounds__(128) void attn_kernel(
    const float* __restrict__ q, const float* __restrict__ k,
    const float* __restrict__ v, float* __restrict__ o)
{
    __shared__ float qs[64 * 64];   // qT[d][i] swizzled
    __shared__ float u [64 * 64];   // kT[d][j] then pT[j][i], swizzled
    __shared__ float vs[64 * 64];   // v[j][d]
    int tid = threadIdx.x;
    int ty = tid >> 4, tx = tid & 15;   // ty 0..7 (q-groups of 8), tx 0..15 (groups of 4)
    int qb = blockIdx.x * 64;
    int head = blockIdx.y, b = blockIdx.z;
    const size_t bs = (size_t)T * DM;
    const float* qp = q + b * bs + head * HD;
    const float* kp = k + b * bs + head * HD;
    const float* vp = v + b * bs + head * HD;
    float* op = o + b * bs + head * HD;

    // Q transposed + swizzled + scaled
    for (int idx = tid; idx < 1024; idx += 128) {
        int i = idx >> 4, c4 = (idx & 15) << 2;
        int t = qb + i;
        float4 val = make_float4(0.f, 0.f, 0.f, 0.f);
        if (t < T) val = *(const float4*)(qp + (size_t)t * DM + c4);
        val.x *= 0.125f; val.y *= 0.125f; val.z *= 0.125f; val.w *= 0.125f;
        int swi = SW(i, c4);
        qs[(c4 + 0) * 64 + swi] = val.x;
        qs[(c4 + 1) * 64 + swi] = val.y;
        qs[(c4 + 2) * 64 + swi] = val.z;
        qs[(c4 + 3) * 64 + swi] = val.w;
    }
    float oa[8][4];
    float mloc[8], lloc[8];
    #pragma unroll
    for (int i = 0; i < 8; i++) {
        mloc[i] = -1e30f; lloc[i] = 0.f;
        #pragma unroll
        for (int j = 0; j < 4; j++) oa[i][j] = 0.f;
    }
    __syncthreads();

    for (int kb = 0; kb < T; kb += 64) {
        // V natural
        for (int idx = tid; idx < 1024; idx += 128) {
            int j = idx >> 4, c4 = (idx & 15) << 2;
            int s = kb + j;
            float4 vv = make_float4(0.f, 0.f, 0.f, 0.f);
            if (s < T) vv = *(const float4*)(vp + (size_t)s * DM + c4);
            *(float4*)&vs[j * 64 + c4] = vv;
        }
        // K transposed + swizzled
        for (int idx = tid; idx < 1024; idx += 128) {
            int j = idx & 63, c4 = (idx >> 6) << 2;
            int s = kb + j;
            float4 kv = make_float4(0.f, 0.f, 0.f, 0.f);
            if (s < T) kv = *(const float4*)(kp + (size_t)s * DM + c4);
            int swj = SW(j, c4);
            u[(c4 + 0) * 64 + swj] = kv.x;
            u[(c4 + 1) * 64 + swj] = kv.y;
            u[(c4 + 2) * 64 + swj] = kv.z;
            u[(c4 + 3) * 64 + swj] = kv.w;
        }
        __syncthreads();

        // S = Q K^T (8x4 per thread)
        float sa[8][4];
        #pragma unroll
        for (int i = 0; i < 8; i++)
            #pragma unroll
            for (int j = 0; j < 4; j++) sa[i][j] = 0.f;
        #pragma unroll 4
        for (int d = 0; d < 64; d++) {
            float a[8];
            *(float4*)&a[0] = *(float4*)&qs[d * 64 + SW(ty << 3, d)];
            *(float4*)&a[4] = *(float4*)&qs[d * 64 + SW((ty << 3) + 4, d)];
            float4 bv = *(float4*)&u[d * 64 + SW(tx << 2, d)];
            #pragma unroll
            for (int i = 0; i < 8; i++) {
                sa[i][0] += a[i] * bv.x; sa[i][1] += a[i] * bv.y;
                sa[i][2] += a[i] * bv.z; sa[i][3] += a[i] * bv.w;
            }
        }
        int rem = T - kb;
        if (rem < 64) {
            #pragma unroll
            for (int jj = 0; jj < 4; jj++)
                if ((tx << 2) + jj >= rem) {
                    #pragma unroll
                    for (int ii = 0; ii < 8; ii++) sa[ii][jj] = -1e30f;
                }
        }
        __syncthreads();   // done reading kT from u

        // online softmax (row groups of 16 lanes), store P^T into u
        #pragma unroll
        for (int ii = 0; ii < 8; ii++) {
            float rmax = fmaxf(fmaxf(sa[ii][0], sa[ii][1]), fmaxf(sa[ii][2], sa[ii][3]));
            #pragma unroll
            for (int off = 8; off >= 1; off >>= 1)
                rmax = fmaxf(rmax, __shfl_xor_sync(0xffffffffu, rmax, off));
            float mnew = fmaxf(mloc[ii], rmax);
            float corr = __expf(mloc[ii] - mnew);
            mloc[ii] = mnew;
            float rsum = 0.f;
            #pragma unroll
            for (int jj = 0; jj < 4; jj++) {
                float p = __expf(sa[ii][jj] - mnew);
                sa[ii][jj] = p; rsum += p;
            }
            #pragma unroll
            for (int off = 8; off >= 1; off >>= 1)
                rsum += __shfl_xor_sync(0xffffffffu, rsum, off);
            lloc[ii] = lloc[ii] * corr + rsum;
            #pragma unroll
            for (int jj = 0; jj < 4; jj++) {
                oa[ii][jj] *= corr;
                int jcol = (tx << 2) + jj;
                u[jcol * 64 + SW((ty << 3) + ii, jcol)] = sa[ii][jj];
            }
        }
        __syncthreads();

        // O += P V
        #pragma unroll 4
        for (int j = 0; j < 64; j++) {
            float a[8];
            *(float4*)&a[0] = *(float4*)&u[j * 64 + SW(ty << 3, j)];
            *(float4*)&a[4] = *(float4*)&u[j * 64 + SW((ty << 3) + 4, j)];
            float4 bv = *(float4*)&vs[j * 64 + (tx << 2)];
            #pragma unroll
            for (int i = 0; i < 8; i++) {
                oa[i][0] += a[i] * bv.x; oa[i][1] += a[i] * bv.y;
                oa[i][2] += a[i] * bv.z; oa[i][3] += a[i] * bv.w;
            }
        }
        __syncthreads();
    }

    #pragma unroll
    for (int ii = 0; ii < 8; ii++) {
        int t = qb + (ty << 3) + ii;
        if (t < T) {
            float inv = 1.f / lloc[ii];
            float4 r = make_float4(oa[ii][0] * inv, oa[ii][1] * inv,
                                   oa[ii][2] * inv, oa[ii][3] * inv);
            *(float4*)(op + (size_t)t * DM + (tx << 2)) = r;
        }
    }
}

// ---------------- residual add + layernorm ----------------
__global__ void add_ln_kernel(float* __restrict__ h, const float* __restrict__ f,
                              const float* __restrict__ gamma, const float* __restrict__ beta)
{
    int row = blockIdx.x;
    int tid = threadIdx.x;  // 128
    float* hr = h + (size_t)row * DM;
    const float* fr = f + (size_t)row * DM;
    float v[4];
    float s = 0.f;
    #pragma unroll
    for (int i = 0; i < 4; i++) {
        v[i] = hr[tid + 128 * i] + fr[tid + 128 * i];
        s += v[i];
    }
    __shared__ float sm[4];
    int lane = tid & 31, warp = tid >> 5;
    #pragma unroll
    for (int off = 16; off >= 1; off >>= 1) s += __shfl_xor_sync(0xffffffffu, s, off);
    if (lane == 0) sm[warp] = s;
    __syncthreads();
    float mean = (sm[0] + sm[1] + sm[2] + sm[3]) * (1.f / DM);
    float vs = 0.f;
    #pragma unroll
    for (int i = 0; i < 4; i++) { float d = v[i] - mean; vs += d * d; }
    __syncthreads();
    #pragma unroll
    for (int off = 16; off >= 1; off >>= 1) vs += __shfl_xor_sync(0xffffffffu, vs, off);
    if (lane == 0) sm[warp] = vs;
    __syncthreads();
    float var = (sm[0] + sm[1] + sm[2] + sm[3]) * (1.f / DM);
    float inv = rsqrtf(var + 1e-5f);
    #pragma unroll
    for (int i = 0; i < 4; i++) {
        int d = tid + 128 * i;
        hr[d] = (v[i] - mean) * inv * gamma[d] + beta[d];
    }
}

// ---------------- classification head ----------------
__global__ void head_kernel(const float* __restrict__ h,
                            const float* __restrict__ Wd1, const float* __restrict__ bd1,
                            const float* __restrict__ Wd2, const float* __restrict__ bd2,
                            float* __restrict__ out)
{
    __shared__ float mid[NB][MLPD];
    int tid = threadIdx.x; // 256
    for (int b = 0; b < NB; b++) {
        const float* cls = h + (size_t)b * T * DM;
        float acc = bd1[tid];
        for (int kk = 0; kk < DM; kk++)
            acc += cls[kk] * Wd1[kk * MLPD + tid];
        mid[b][tid] = acc;
    }
    __syncthreads();
    if (tid < NB * CLASSES) {
        int b = tid / CLASSES, c = tid % CLASSES;
        float acc = bd2[c];
        for (int m = 0; m < MLPD; m++)
            acc += mid[b][m] * Wd2[m * CLASSES + c];
        out[b * CLASSES + c] = acc;
    }
}

// ---------------- GAT branch ----------------
__global__ __launch_bounds__(64) void gat_kernel(
    const float* __restrict__ x, const int* __restrict__ adj,
    const float* __restrict__ Wg, const float* __restrict__ ag,
    const float* __restrict__ Wgo, const float* __restrict__ ago,
    float* __restrict__ out)
{
    int gidx = blockIdx.x;
    int s = gidx / 5, g = gidx % 5;
    int tid = threadIdx.x;
    int lane = tid & 31, warp = tid >> 5;

    __shared__ float xg[5][3];
    __shared__ float hcat[5][GH * GHID];
    __shared__ float att[5][5];
    __shared__ float s1[5], s2[5];
    __shared__ float red[2][5][2];
    __shared__ int msk[25];
    __shared__ float h2[5][5];
    __shared__ float o2[5][5];

    if (tid < 15) {
        int n = tid / 3, c = tid % 3;
        xg[n][c] = x[(size_t)n * SEQ * NTOK + (size_t)s * NTOK + g * 3 + c];
    }
    if (tid < 25) msk[tid] = adj[tid];
    __syncthreads();

    for (int head = 0; head < GH; head++) {
        const float* W = Wg + head * 3 * GHID;
        float hval[5];
        #pragma unroll
        for (int n = 0; n < 5; n++)
            hval[n] = xg[n][0] * W[tid] + xg[n][1] * W[GHID + tid] + xg[n][2] * W[2 * GHID + tid];
        float a1 = ag[head * 2 * GHID + tid];
        float a2 = ag[head * 2 * GHID + GHID + tid];
        #pragma unroll
        for (int n = 0; n < 5; n++) {
            float p1 = hval[n] * a1, p2 = hval[n] * a2;
            #pragma unroll
            for (int off = 16; off >= 1; off >>= 1) {
                p1 += __shfl_xor_sync(0xffffffffu, p1, off);
                p2 += __shfl_xor_sync(0xffffffffu, p2, off);
            }
            if (lane == 0) { red[warp][n][0] = p1; red[warp][n][1] = p2; }
        }
        __syncthreads();
        if (tid < 5) {
            s1[tid] = red[0][tid][0] + red[1][tid][0];
            s2[tid] = red[0][tid][1] + red[1][tid][1];
        }
        __syncthreads();
        if (tid < 5) {
            int i = tid;
            float ev[5]; float mx = -1e30f;
            #pragma unroll
            for (int j = 0; j < 5; j++) {
                if (msk[i * 5 + j]) {
                    float e = s1[i] + s2[j];
                    e = e > 0.f ? e : 0.2f * e;
                    ev[j] = e;
                    if (e > mx) mx = e;
                } else ev[j] = -1e30f;
            }
            float sum = 0.f;
            #pragma unroll
            for (int j = 0; j < 5; j++) {
                float p = msk[i * 5 + j] ? __expf(ev[j] - mx) : 0.f;
                att[i][j] = p; sum += p;
            }
            float invs = 1.f / sum;
            #pragma unroll
            for (int j = 0; j < 5; j++) att[i][j] *= invs;
        }
        __syncthreads();
        #pragma unroll
        for (int n = 0; n < 5; n++) {
            float o = att[n][0] * hval[0] + att[n][1] * hval[1] + att[n][2] * hval[2]
                    + att[n][3] * hval[3] + att[n][4] * hval[4];
            o = o > 0.f ? o : expm1f(o);
            hcat[n][head * GHID + tid] = o;
        }
        __syncthreads();
    }

    if (tid < 25) {
        int n = tid / 5, m = tid % 5;
        float acc = 0.f;
        for (int kk = 0; kk < GH * GHID; kk++)
            acc += hcat[n][kk] * Wgo[kk * GCLS + m];
        h2[n][m] = acc;
    }
    __syncthreads();
    if (tid < 5) {
        float a1 = 0.f, a2 = 0.f;
        #pragma unroll
        for (int m = 0; m < 5; m++) {
            a1 += h2[tid][m] * ago[m];
            a2 += h2[tid][m] * ago[GCLS + m];
        }
        s1[tid] = a1; s2[tid] = a2;
    }
    __syncthreads();
    if (tid < 5) {
        int i = tid;
        float ev[5]; float mx = -1e30f;
        #pragma unroll
        for (int j = 0; j < 5; j++) {
            if (msk[i * 5 + j]) {
                float e = s1[i] + s2[j];
                e = e > 0.f ? e : 0.2f * e;
                ev[j] = e;
                if (e > mx) mx = e;
            } else ev[j] = -1e30f;
        }
        float sum = 0.f;
        #pragma unroll
        for (int j = 0; j < 5; j++) {
            float p = msk[i * 5 + j] ? __expf(ev[j] - mx) : 0.f;
            att[i][j] = p; sum += p;
        }
        float invs = 1.f / sum;
        #pragma unroll
        for (int j = 0; j < 5; j++) att[i][j] *= invs;
    }
    __syncthreads();
    if (tid < 25) {
        int n = tid / 5, m = tid % 5;
        float o = 0.f;
        #pragma unroll
        for (int j = 0; j < 5; j++) o += att[n][j] * h2[j][m];
        o = o > 0.f ? o : expm1f(o);
        o2[n][m] = o;
    }
    __syncthreads();
    if (tid < 5) {
        int n = tid;
        float mx = -1e30f;
        #pragma unroll
        for (int m = 0; m < 5; m++) mx = fmaxf(mx, o2[n][m]);
        float sum = 0.f;
        #pragma unroll
        for (int m = 0; m < 5; m++) sum += __expf(o2[n][m] - mx);
        float lse = mx + logf(sum);
        #pragma unroll
        for (int m = 0; m < 5; m++)
            out[OUT_GAT_BASE + (size_t)gidx * 25 + n * 5 + m] = o2[n][m] - lse;
    }
}

// ---------------- host orchestration ----------------
extern "C" void kernel_launch(void* const* d_in, const int* in_sizes, int n_in,
                              void* d_out, int out_size)
{
    const float* x       = (const float*)d_in[0];
    const int*   adj     = (const int*)  d_in[1];
    const float* W_enc   = (const float*)d_in[2];
    const float* b_enc   = (const float*)d_in[3];
    const float* cls_tok = (const float*)d_in[4];
    const float* pos_emb = (const float*)d_in[5];
    const float* Wq      = (const float*)d_in[6];
    const float* bq      = (const float*)d_in[7];
    const float* Wk      = (const float*)d_in[8];
    const float* bk      = (const float*)d_in[9];
    const float* Wv      = (const float*)d_in[10];
    const float* bv      = (const float*)d_in[11];
    const float* Wo      = (const float*)d_in[12];
    const float* bo      = (const float*)d_in[13];
    const float* W1      = (const float*)d_in[14];
    const float* b1      = (const float*)d_in[15];
    const float* W2      = (const float*)d_in[16];
    const float* b2      = (const float*)d_in[17];
    const float* g1      = (const float*)d_in[18];
    const float* be1     = (const float*)d_in[19];
    const float* g2      = (const float*)d_in[20];
    const float* be2     = (const float*)d_in[21];
    const float* Wd1     = (const float*)d_in[22];
    const float* bd1     = (const float*)d_in[23];
    const float* Wd2     = (const float*)d_in[24];
    const float* bd2     = (const float*)d_in[25];
    const float* Wg      = (const float*)d_in[26];
    const float* ag      = (const float*)d_in[27];
    const float* Wgo     = (const float*)d_in[28];
    const float* ago     = (const float*)d_in[29];
    float* out = (float*)d_out;

    float *h, *q, *k, *v, *ao, *t, *ff;
    cudaGetSymbolAddress((void**)&h,  g_h);
    cudaGetSymbolAddress((void**)&q,  g_q);
    cudaGetSymbolAddress((void**)&k,  g_k);
    cudaGetSymbolAddress((void**)&v,  g_v);
    cudaGetSymbolAddress((void**)&ao, g_ao);
    cudaGetSymbolAddress((void**)&t,  g_t);
    cudaGetSymbolAddress((void**)&ff, g_ff);

    gat_kernel<<<GAT_GRAPHS, 64>>>(x, adj, Wg, ag, Wgo, ago, out);
    enc_kernel<<<MROWS, 128>>>(x, W_enc, b_enc, cls_tok, pos_emb, h);

    dim3 gemm_tb(256);
    dim3 grid_dm(DM / 128, (MROWS + 127) / 128);    // 4 x 41
    dim3 grid_ff(DFF / 128, (MROWS + 127) / 128);   // 16 x 41
    dim3 attn_grid((T + 63) / 64, NHEAD, NB);

    for (int l = 0; l < NL; l++) {
        gemm_kernel<<<grid_dm, gemm_tb>>>(h, Wq + (size_t)l * DM * DM, bq + l * DM, q, MROWS, DM, DM, 0);
        gemm_kernel<<<grid_dm, gemm_tb>>>(h, Wk + (size_t)l * DM * DM, bk + l * DM, k, MROWS, DM, DM, 0);
        gemm_kernel<<<grid_dm, gemm_tb>>>(h, Wv + (size_t)l * DM * DM, bv + l * DM, v, MROWS, DM, DM, 0);
        attn_kernel<<<attn_grid, 128>>>(q, k, v, ao);
        gemm_kernel<<<grid_dm, gemm_tb>>>(ao, Wo + (size_t)l * DM * DM, bo + l * DM, t, MROWS, DM, DM, 0);
        add_ln_kernel<<<MROWS, 128>>>(h, t, g1 + l * DM, be1 + l * DM);
        gemm_kernel<<<grid_ff, gemm_tb>>>(h, W1 + (size_t)l * DM * DFF, b1 + l * DFF, ff, MROWS, DFF, DM, 1);
        gemm_kernel<<<grid_dm, gemm_tb>>>(ff, W2 + (size_t)l * DFF * DM, b2 + l * DM, t, MROWS, DM, DFF, 0);
        add_ln_kernel<<<MROWS, 128>>>(h, t, g2 + l * DM, be2 + l * DM);
    }

    head_kernel<<<1, 256>>>(h, Wd1, bd1, Wd2, bd2, out);
}

// round 4
// speedup vs baseline: 1.6326x; 1.6326x over previous
#include <cuda_runtime.h>
#include <cuda_bf16.h>
#include <math.h>
#include <stdint.h>

// ---------------- problem constants ----------------
#define NB 5
#define SEQ 1024
#define T 1025
#define DM 512
#define NHEAD 8
#define HD 64
#define DFF 2048
#define NL 4
#define NTOK 51
#define MLPD 256
#define CLASSES 7
#define GH 3
#define GHID 64
#define GCLS 5
#define MROWS (NB * T)
#define GAT_GRAPHS (SEQ * 5)
#define OUT_GAT_BASE (NB * CLASSES)

// attention swizzle
#define SW(i, r) ((i) ^ ((((r) >> 2) & 7) << 2))

// ---------------- scratch ----------------
__device__ float g_h [MROWS * DM];
__device__ float g_q [MROWS * DM];
__device__ float g_k [MROWS * DM];
__device__ float g_v [MROWS * DM];
__device__ float g_ao[MROWS * DM];
__device__ float g_t [MROWS * DM];
__device__ float g_ff[MROWS * DFF];
// transposed (tf32-rounded) weights
__device__ float g_WqT[NL * DM * DM];
__device__ float g_WkT[NL * DM * DM];
__device__ float g_WvT[NL * DM * DM];
__device__ float g_WoT[NL * DM * DM];
__device__ float g_W1T[NL * DM * DFF];
__device__ float g_W2T[NL * DFF * DM];

// ---------------- helpers ----------------
__device__ __forceinline__ uint32_t ftf32(float x) {
    uint32_t r;
    asm("cvt.rna.tf32.f32 %0, %1;" : "=r"(r) : "f"(x));
    return r;
}

#define MMA_TF32(d, a, b) \
    asm volatile("mma.sync.aligned.m16n8k8.row.col.f32.tf32.tf32.f32 " \
        "{%0,%1,%2,%3}, {%4,%5,%6,%7}, {%8,%9}, {%0,%1,%2,%3};" \
        : "+f"((d)[0]), "+f"((d)[1]), "+f"((d)[2]), "+f"((d)[3]) \
        : "r"((a).x), "r"((a).y), "r"((a).z), "r"((a).w), \
          "r"((b).x), "r"((b).y))

// ---------------- weight transpose + tf32 round: Wt[n][k] = tf32(W[k][n]) ----------------
__global__ void transpose_tf32(const float* __restrict__ W, float* __restrict__ Wt, int K, int N)
{
    __shared__ float t[32][33];
    const float* w = W + (size_t)blockIdx.z * K * N;
    float* o = Wt + (size_t)blockIdx.z * K * N;
    int n0 = blockIdx.x * 32, k0 = blockIdx.y * 32;
    int tx = threadIdx.x, ty = threadIdx.y;   // 32 x 8
    #pragma unroll
    for (int i = 0; i < 32; i += 8)
        t[ty + i][tx] = w[(size_t)(k0 + ty + i) * N + n0 + tx];
    __syncthreads();
    #pragma unroll
    for (int i = 0; i < 32; i += 8)
        o[(size_t)(n0 + ty + i) * K + k0 + tx] = __uint_as_float(ftf32(t[tx][ty + i]));
}

// ---------------- tf32 mma.sync GEMM: C = A(MxK) @ Bt^T + bias ----------------
// Bt is [N][K] row-major, pre-rounded to tf32. 128x128x32 CTA tile, 8 warps,
// 64x32 warp tile (4x4 grid of m16n8k8), fragment-major SMEM staging,
// register-double-buffered global loads, ping-pong SMEM.
// SMEM per buffer: A 4096 floats, B 4096 floats. Total dynamic 64KB.
#define MM_SMEM 65536

__device__ __forceinline__ void mma_gemm_body(
    const float* __restrict__ A, const float* __restrict__ Bt,
    const float* __restrict__ bias, float* __restrict__ C,
    int M, int N, int K, int relu)
{
    extern __shared__ float sm[];
    // layout: As[2][4096] at 0, Bs[2][4096] at 8192
    int tid = threadIdx.x;
    int w = tid >> 5, lane = tid & 31;
    int bm = blockIdx.y * 128, bn = blockIdx.x * 128;
    int wm = (w & 1) * 64;      // warp row offset in tile
    int wn = (w >> 1) * 32;     // warp col offset in tile

    float d[4][4][4];
    #pragma unroll
    for (int i = 0; i < 4; i++)
        #pragma unroll
        for (int j = 0; j < 4; j++)
            #pragma unroll
            for (int e = 0; e < 4; e++) d[i][j][e] = 0.f;

    // per-thread staging coordinates (same for A and B index pattern)
    // idx = tid + it*256; r = idx>>3 (0..127), c4 = (idx&7)<<2 (0..28)
    uint4 ra[4], rb[4];

    int nch = K >> 5;

    // ---- prologue: load chunk 0 ----
    #pragma unroll
    for (int it = 0; it < 4; it++) {
        int idx = tid + it * 256;
        int r = idx >> 3, c4 = (idx & 7) << 2;
        float4 av = make_float4(0.f, 0.f, 0.f, 0.f);
        if (bm + r < M) av = *(const float4*)(A + (size_t)(bm + r) * K + c4);
        ra[it].x = ftf32(av.x); ra[it].y = ftf32(av.y);
        ra[it].z = ftf32(av.z); ra[it].w = ftf32(av.w);
        rb[it] = *(const uint4*)(Bt + (size_t)(bn + r) * K + c4);
    }
    // store chunk 0 into buffer 0
    {
        uint32_t* As = (uint32_t*)sm;
        uint32_t* Bs = (uint32_t*)sm + 8192;
        #pragma unroll
        for (int it = 0; it < 4; it++) {
            int idx = tid + it * 256;
            int r = idx >> 3, c4 = (idx & 7) << 2;
            int kt = c4 >> 3, kin0 = c4 & 7;
            int mt = r >> 4, rin = r & 15;
            int regA = (kin0 ? 2 : 0) + ((rin >> 3) & 1);
            uint32_t* dA = As + ((kt * 8 + mt) * 32 + (rin & 7) * 4) * 4 + regA;
            dA[0] = ra[it].x; dA[4] = ra[it].y; dA[8] = ra[it].z; dA[12] = ra[it].w;
            int nt = r >> 3, nin = r & 7;
            int regB = kin0 ? 1 : 0;
            uint32_t* dB = Bs + ((kt * 16 + nt) * 32 + nin * 4) * 2 + regB;
            dB[0] = rb[it].x; dB[2] = rb[it].y; dB[4] = rb[it].z; dB[6] = rb[it].w;
        }
    }
    __syncthreads();

    for (int c = 0; c < nch; c++) {
        int buf = c & 1;
        uint32_t* As = (uint32_t*)sm + buf * 4096;
        uint32_t* Bs = (uint32_t*)sm + 8192 + buf * 4096;

        // prefetch next chunk into registers
        if (c + 1 < nch) {
            int k0 = (c + 1) << 5;
            #pragma unroll
            for (int it = 0; it < 4; it++) {
                int idx = tid + it * 256;
                int r = idx >> 3, c4 = (idx & 7) << 2;
                float4 av = make_float4(0.f, 0.f, 0.f, 0.f);
                if (bm + r < M) av = *(const float4*)(A + (size_t)(bm + r) * K + k0 + c4);
                ra[it].x = ftf32(av.x); ra[it].y = ftf32(av.y);
                ra[it].z = ftf32(av.z); ra[it].w = ftf32(av.w);
                rb[it] = *(const uint4*)(Bt + (size_t)(bn + r) * K + k0 + c4);
            }
        }

        // compute: 4 k-steps of 8
        #pragma unroll
        for (int kt = 0; kt < 4; kt++) {
            uint4 af[4];
            uint2 bf[4];
            #pragma unroll
            for (int i = 0; i < 4; i++)
                af[i] = *(uint4*)(As + ((kt * 8 + (wm >> 4) + i) * 32 + lane) * 4);
            #pragma unroll
            for (int j = 0; j < 4; j++)
                bf[j] = *(uint2*)(Bs + ((kt * 16 + (wn >> 3) + j) * 32 + lane) * 2);
            #pragma unroll
            for (int i = 0; i < 4; i++)
                #pragma unroll
                for (int j = 0; j < 4; j++)
                    MMA_TF32(d[i][j], af[i], bf[j]);
        }
        __syncthreads();

        // store prefetched chunk into other buffer
        if (c + 1 < nch) {
            uint32_t* As2 = (uint32_t*)sm + (buf ^ 1) * 4096;
            uint32_t* Bs2 = (uint32_t*)sm + 8192 + (buf ^ 1) * 4096;
            #pragma unroll
            for (int it = 0; it < 4; it++) {
                int idx = tid + it * 256;
                int r = idx >> 3, c4 = (idx & 7) << 2;
                int kt = c4 >> 3, kin0 = c4 & 7;
                int mt = r >> 4, rin = r & 15;
                int regA = (kin0 ? 2 : 0) + ((rin >> 3) & 1);
                uint32_t* dA = As2 + ((kt * 8 + mt) * 32 + (rin & 7) * 4) * 4 + regA;
                dA[0] = ra[it].x; dA[4] = ra[it].y; dA[8] = ra[it].z; dA[12] = ra[it].w;
                int nt = r >> 3, nin = r & 7;
                int regB = kin0 ? 1 : 0;
                uint32_t* dB = Bs2 + ((kt * 16 + nt) * 32 + nin * 4) * 2 + regB;
                dB[0] = rb[it].x; dB[2] = rb[it].y; dB[4] = rb[it].z; dB[6] = rb[it].w;
            }
            __syncthreads();
        }
    }

    // ---- epilogue ----
    int g = lane >> 2, t2 = (lane & 3) << 1;
    #pragma unroll
    for (int i = 0; i < 4; i++) {
        #pragma unroll
        for (int hh = 0; hh < 2; hh++) {
            int row = bm + wm + i * 16 + g + hh * 8;
            if (row >= M) continue;
            #pragma unroll
            for (int j = 0; j < 4; j++) {
                int col = bn + wn + j * 8 + t2;
                float2 bb = *(const float2*)(bias + col);
                float2 r;
                r.x = d[i][j][hh * 2 + 0] + bb.x;
                r.y = d[i][j][hh * 2 + 1] + bb.y;
                if (relu) { r.x = fmaxf(r.x, 0.f); r.y = fmaxf(r.y, 0.f); }
                *(float2*)(C + (size_t)row * N + col) = r;
            }
        }
    }
}

__global__ __launch_bounds__(256) void mma_gemm(
    const float* __restrict__ A, const float* __restrict__ Bt,
    const float* __restrict__ bias, float* __restrict__ C,
    int M, int N, int K, int relu)
{
    mma_gemm_body(A, Bt, bias, C, M, N, K, relu);
}

__global__ __launch_bounds__(256) void mma_gemm_qkv(
    const float* __restrict__ A,
    const float* __restrict__ WqT, const float* __restrict__ WkT, const float* __restrict__ WvT,
    const float* __restrict__ bq, const float* __restrict__ bk, const float* __restrict__ bv,
    float* __restrict__ q, float* __restrict__ k, float* __restrict__ v)
{
    const float* Bt; const float* bias; float* C;
    if (blockIdx.z == 0)      { Bt = WqT; bias = bq; C = q; }
    else if (blockIdx.z == 1) { Bt = WkT; bias = bk; C = k; }
    else                      { Bt = WvT; bias = bv; C = v; }
    mma_gemm_body(A, Bt, bias, C, MROWS, DM, DM, 0);
}

// ---------------- encoder ----------------
__global__ void enc_kernel(const float* __restrict__ x,
                           const float* __restrict__ W_enc,
                           const float* __restrict__ b_enc,
                           const float* __restrict__ cls_tok,
                           const float* __restrict__ pos_emb,
                           float* __restrict__ h)
{
    int row = blockIdx.x;
    int b = row / T, t = row % T;
    int tid = threadIdx.x;           // 128
    float* hr = h + (size_t)row * DM;
    if (t == 0) {
        for (int d = tid; d < DM; d += 128)
            hr[d] = cls_tok[d] + pos_emb[d];
        return;
    }
    __shared__ float xs[NTOK];
    if (tid < NTOK) xs[tid] = x[(size_t)b * SEQ * NTOK + (size_t)(t - 1) * NTOK + tid];
    __syncthreads();
    for (int d = tid; d < DM; d += 128) {
        float acc = b_enc[d] + pos_emb[(size_t)t * DM + d];
        #pragma unroll 17
        for (int kk = 0; kk < NTOK; kk++)
            acc += xs[kk] * W_enc[kk * DM + d];
        hr[d] = acc;
    }
}

// ---------------- flash attention (fp32 CUDA cores) ----------------
__global__ __launch_bounds__(128) void attn_kernel(
    const float* __restrict__ q, const float* __restrict__ k,
    const float* __restrict__ v, float* __restrict__ o)
{
    __shared__ float qs[64 * 64];
    __shared__ float u [64 * 64];
    __shared__ float vs[64 * 64];
    int tid = threadIdx.x;
    int ty = tid >> 4, tx = tid & 15;
    int qb = blockIdx.x * 64;
    int head = blockIdx.y, b = blockIdx.z;
    const size_t bs = (size_t)T * DM;
    const float* qp = q + b * bs + head * HD;
    const float* kp = k + b * bs + head * HD;
    const float* vp = v + b * bs + head * HD;
    float* op = o + b * bs + head * HD;

    for (int idx = tid; idx < 1024; idx += 128) {
        int i = idx >> 4, c4 = (idx & 15) << 2;
        int t = qb + i;
        float4 val = make_float4(0.f, 0.f, 0.f, 0.f);
        if (t < T) val = *(const float4*)(qp + (size_t)t * DM + c4);
        val.x *= 0.125f; val.y *= 0.125f; val.z *= 0.125f; val.w *= 0.125f;
        int swi = SW(i, c4);
        qs[(c4 + 0) * 64 + swi] = val.x;
        qs[(c4 + 1) * 64 + swi] = val.y;
        qs[(c4 + 2) * 64 + swi] = val.z;
        qs[(c4 + 3) * 64 + swi] = val.w;
    }
    float oa[8][4];
    float mloc[8], lloc[8];
    #pragma unroll
    for (int i = 0; i < 8; i++) {
        mloc[i] = -1e30f; lloc[i] = 0.f;
        #pragma unroll
        for (int j = 0; j < 4; j++) oa[i][j] = 0.f;
    }
    __syncthreads();

    for (int kb = 0; kb < T; kb += 64) {
        for (int idx = tid; idx < 1024; idx += 128) {
            int j = idx >> 4, c4 = (idx & 15) << 2;
            int s = kb + j;
            float4 vv = make_float4(0.f, 0.f, 0.f, 0.f);
            if (s < T) vv = *(const float4*)(vp + (size_t)s * DM + c4);
            *(float4*)&vs[j * 64 + c4] = vv;
        }
        for (int idx = tid; idx < 1024; idx += 128) {
            int j = idx & 63, c4 = (idx >> 6) << 2;
            int s = kb + j;
            float4 kv = make_float4(0.f, 0.f, 0.f, 0.f);
            if (s < T) kv = *(const float4*)(kp + (size_t)s * DM + c4);
            int swj = SW(j, c4);
            u[(c4 + 0) * 64 + swj] = kv.x;
            u[(c4 + 1) * 64 + swj] = kv.y;
            u[(c4 + 2) * 64 + swj] = kv.z;
            u[(c4 + 3) * 64 + swj] = kv.w;
        }
        __syncthreads();

        float sa[8][4];
        #pragma unroll
        for (int i = 0; i < 8; i++)
            #pragma unroll
            for (int j = 0; j < 4; j++) sa[i][j] = 0.f;
        #pragma unroll 4
        for (int d = 0; d < 64; d++) {
            float a[8];
            *(float4*)&a[0] = *(float4*)&qs[d * 64 + SW(ty << 3, d)];
            *(float4*)&a[4] = *(float4*)&qs[d * 64 + SW((ty << 3) + 4, d)];
            float4 bv = *(float4*)&u[d * 64 + SW(tx << 2, d)];
            #pragma unroll
            for (int i = 0; i < 8; i++) {
                sa[i][0] += a[i] * bv.x; sa[i][1] += a[i] * bv.y;
                sa[i][2] += a[i] * bv.z; sa[i][3] += a[i] * bv.w;
            }
        }
        int rem = T - kb;
        if (rem < 64) {
            #pragma unroll
            for (int jj = 0; jj < 4; jj++)
                if ((tx << 2) + jj >= rem) {
                    #pragma unroll
                    for (int ii = 0; ii < 8; ii++) sa[ii][jj] = -1e30f;
                }
        }
        __syncthreads();

        #pragma unroll
        for (int ii = 0; ii < 8; ii++) {
            float rmax = fmaxf(fmaxf(sa[ii][0], sa[ii][1]), fmaxf(sa[ii][2], sa[ii][3]));
            #pragma unroll
            for (int off = 8; off >= 1; off >>= 1)
                rmax = fmaxf(rmax, __shfl_xor_sync(0xffffffffu, rmax, off));
            float mnew = fmaxf(mloc[ii], rmax);
            float corr = __expf(mloc[ii] - mnew);
            mloc[ii] = mnew;
            float rsum = 0.f;
            #pragma unroll
            for (int jj = 0; jj < 4; jj++) {
                float p = __expf(sa[ii][jj] - mnew);
                sa[ii][jj] = p; rsum += p;
            }
            #pragma unroll
            for (int off = 8; off >= 1; off >>= 1)
                rsum += __shfl_xor_sync(0xffffffffu, rsum, off);
            lloc[ii] = lloc[ii] * corr + rsum;
            #pragma unroll
            for (int jj = 0; jj < 4; jj++) {
                oa[ii][jj] *= corr;
                int jcol = (tx << 2) + jj;
                u[jcol * 64 + SW((ty << 3) + ii, jcol)] = sa[ii][jj];
            }
        }
        __syncthreads();

        #pragma unroll 4
        for (int j = 0; j < 64; j++) {
            float a[8];
            *(float4*)&a[0] = *(float4*)&u[j * 64 + SW(ty << 3, j)];
            *(float4*)&a[4] = *(float4*)&u[j * 64 + SW((ty << 3) + 4, j)];
            float4 bv = *(float4*)&vs[j * 64 + (tx << 2)];
            #pragma unroll
            for (int i = 0; i < 8; i++) {
                oa[i][0] += a[i] * bv.x; oa[i][1] += a[i] * bv.y;
                oa[i][2] += a[i] * bv.z; oa[i][3] += a[i] * bv.w;
            }
        }
        __syncthreads();
    }

    #pragma unroll
    for (int ii = 0; ii < 8; ii++) {
        int t = qb + (ty << 3) + ii;
        if (t < T) {
            float inv = 1.f / lloc[ii];
            float4 r = make_float4(oa[ii][0] * inv, oa[ii][1] * inv,
                                   oa[ii][2] * inv, oa[ii][3] * inv);
            *(float4*)(op + (size_t)t * DM + (tx << 2)) = r;
        }
    }
}

// ---------------- residual add + layernorm ----------------
__global__ void add_ln_kernel(float* __restrict__ h, const float* __restrict__ f,
                              const float* __restrict__ gamma, const float* __restrict__ beta)
{
    int row = blockIdx.x;
    int tid = threadIdx.x;  // 128
    float* hr = h + (size_t)row * DM;
    const float* fr = f + (size_t)row * DM;
    float v[4];
    float s = 0.f;
    #pragma unroll
    for (int i = 0; i < 4; i++) {
        v[i] = hr[tid + 128 * i] + fr[tid + 128 * i];
        s += v[i];
    }
    __shared__ float sm[4];
    int lane = tid & 31, warp = tid >> 5;
    #pragma unroll
    for (int off = 16; off >= 1; off >>= 1) s += __shfl_xor_sync(0xffffffffu, s, off);
    if (lane == 0) sm[warp] = s;
    __syncthreads();
    float mean = (sm[0] + sm[1] + sm[2] + sm[3]) * (1.f / DM);
    float vs = 0.f;
    #pragma unroll
    for (int i = 0; i < 4; i++) { float d = v[i] - mean; vs += d * d; }
    __syncthreads();
    #pragma unroll
    for (int off = 16; off >= 1; off >>= 1) vs += __shfl_xor_sync(0xffffffffu, vs, off);
    if (lane == 0) sm[warp] = vs;
    __syncthreads();
    float var = (sm[0] + sm[1] + sm[2] + sm[3]) * (1.f / DM);
    float inv = rsqrtf(var + 1e-5f);
    #pragma unroll
    for (int i = 0; i < 4; i++) {
        int d = tid + 128 * i;
        hr[d] = (v[i] - mean) * inv * gamma[d] + beta[d];
    }
}

// ---------------- classification head ----------------
__global__ void head_kernel(const float* __restrict__ h,
                            const float* __restrict__ Wd1, const float* __restrict__ bd1,
                            const float* __restrict__ Wd2, const float* __restrict__ bd2,
                            float* __restrict__ out)
{
    __shared__ float mid[NB][MLPD];
    int tid = threadIdx.x; // 256
    for (int b = 0; b < NB; b++) {
        const float* cls = h + (size_t)b * T * DM;
        float acc = bd1[tid];
        for (int kk = 0; kk < DM; kk++)
            acc += cls[kk] * Wd1[kk * MLPD + tid];
        mid[b][tid] = acc;
    }
    __syncthreads();
    if (tid < NB * CLASSES) {
        int b = tid / CLASSES, c = tid % CLASSES;
        float acc = bd2[c];
        for (int m = 0; m < MLPD; m++)
            acc += mid[b][m] * Wd2[m * CLASSES + c];
        out[b * CLASSES + c] = acc;
    }
}

// ---------------- GAT branch ----------------
__global__ __launch_bounds__(64) void gat_kernel(
    const float* __restrict__ x, const int* __restrict__ adj,
    const float* __restrict__ Wg, const float* __restrict__ ag,
    const float* __restrict__ Wgo, const float* __restrict__ ago,
    float* __restrict__ out)
{
    int gidx = blockIdx.x;
    int s = gidx / 5, g = gidx % 5;
    int tid = threadIdx.x;
    int lane = tid & 31, warp = tid >> 5;

    __shared__ float xg[5][3];
    __shared__ float hcat[5][GH * GHID];
    __shared__ float att[5][5];
    __shared__ float s1[5], s2[5];
    __shared__ float red[2][5][2];
    __shared__ int msk[25];
    __shared__ float h2[5][5];
    __shared__ float o2[5][5];

    if (tid < 15) {
        int n = tid / 3, c = tid % 3;
        xg[n][c] = x[(size_t)n * SEQ * NTOK + (size_t)s * NTOK + g * 3 + c];
    }
    if (tid < 25) msk[tid] = adj[tid];
    __syncthreads();

    for (int head = 0; head < GH; head++) {
        const float* W = Wg + head * 3 * GHID;
        float hval[5];
        #pragma unroll
        for (int n = 0; n < 5; n++)
            hval[n] = xg[n][0] * W[tid] + xg[n][1] * W[GHID + tid] + xg[n][2] * W[2 * GHID + tid];
        float a1 = ag[head * 2 * GHID + tid];
        float a2 = ag[head * 2 * GHID + GHID + tid];
        #pragma unroll
        for (int n = 0; n < 5; n++) {
            float p1 = hval[n] * a1, p2 = hval[n] * a2;
            #pragma unroll
            for (int off = 16; off >= 1; off >>= 1) {
                p1 += __shfl_xor_sync(0xffffffffu, p1, off);
                p2 += __shfl_xor_sync(0xffffffffu, p2, off);
            }
            if (lane == 0) { red[warp][n][0] = p1; red[warp][n][1] = p2; }
        }
        __syncthreads();
        if (tid < 5) {
            s1[tid] = red[0][tid][0] + red[1][tid][0];
            s2[tid] = red[0][tid][1] + red[1][tid][1];
        }
        __syncthreads();
        if (tid < 5) {
            int i = tid;
            float ev[5]; float mx = -1e30f;
            #pragma unroll
            for (int j = 0; j < 5; j++) {
                if (msk[i * 5 + j]) {
                    float e = s1[i] + s2[j];
                    e = e > 0.f ? e : 0.2f * e;
                    ev[j] = e;
                    if (e > mx) mx = e;
                } else ev[j] = -1e30f;
            }
            float sum = 0.f;
            #pragma unroll
            for (int j = 0; j < 5; j++) {
                float p = msk[i * 5 + j] ? __expf(ev[j] - mx) : 0.f;
                att[i][j] = p; sum += p;
            }
            float invs = 1.f / sum;
            #pragma unroll
            for (int j = 0; j < 5; j++) att[i][j] *= invs;
        }
        __syncthreads();
        #pragma unroll
        for (int n = 0; n < 5; n++) {
            float o = att[n][0] * hval[0] + att[n][1] * hval[1] + att[n][2] * hval[2]
                    + att[n][3] * hval[3] + att[n][4] * hval[4];
            o = o > 0.f ? o : expm1f(o);
            hcat[n][head * GHID + tid] = o;
        }
        __syncthreads();
    }

    if (tid < 25) {
        int n = tid / 5, m = tid % 5;
        float acc = 0.f;
        for (int kk = 0; kk < GH * GHID; kk++)
            acc += hcat[n][kk] * Wgo[kk * GCLS + m];
        h2[n][m] = acc;
    }
    __syncthreads();
    if (tid < 5) {
        float a1 = 0.f, a2 = 0.f;
        #pragma unroll
        for (int m = 0; m < 5; m++) {
            a1 += h2[tid][m] * ago[m];
            a2 += h2[tid][m] * ago[GCLS + m];
        }
        s1[tid] = a1; s2[tid] = a2;
    }
    __syncthreads();
    if (tid < 5) {
        int i = tid;
        float ev[5]; float mx = -1e30f;
        #pragma unroll
        for (int j = 0; j < 5; j++) {
            if (msk[i * 5 + j]) {
                float e = s1[i] + s2[j];
                e = e > 0.f ? e : 0.2f * e;
                ev[j] = e;
                if (e > mx) mx = e;
            } else ev[j] = -1e30f;
        }
        float sum = 0.f;
        #pragma unroll
        for (int j = 0; j < 5; j++) {
            float p = msk[i * 5 + j] ? __expf(ev[j] - mx) : 0.f;
            att[i][j] = p; sum += p;
        }
        float invs = 1.f / sum;
        #pragma unroll
        for (int j = 0; j < 5; j++) att[i][j] *= invs;
    }
    __syncthreads();
    if (tid < 25) {
        int n = tid / 5, m = tid % 5;
        float o = 0.f;
        #pragma unroll
        for (int j = 0; j < 5; j++) o += att[n][j] * h2[j][m];
        o = o > 0.f ? o : expm1f(o);
        o2[n][m] = o;
    }
    __syncthreads();
    if (tid < 5) {
        int n = tid;
        float mx = -1e30f;
        #pragma unroll
        for (int m = 0; m < 5; m++) mx = fmaxf(mx, o2[n][m]);
        float sum = 0.f;
        #pragma unroll
        for (int m = 0; m < 5; m++) sum += __expf(o2[n][m] - mx);
        float lse = mx + logf(sum);
        #pragma unroll
        for (int m = 0; m < 5; m++)
            out[OUT_GAT_BASE + (size_t)gidx * 25 + n * 5 + m] = o2[n][m] - lse;
    }
}

// ---------------- host orchestration ----------------
extern "C" void kernel_launch(void* const* d_in, const int* in_sizes, int n_in,
                              void* d_out, int out_size)
{
    const float* x       = (const float*)d_in[0];
    const int*   adj     = (const int*)  d_in[1];
    const float* W_enc   = (const float*)d_in[2];
    const float* b_enc   = (const float*)d_in[3];
    const float* cls_tok = (const float*)d_in[4];
    const float* pos_emb = (const float*)d_in[5];
    const float* Wq      = (const float*)d_in[6];
    const float* bq      = (const float*)d_in[7];
    const float* Wk      = (const float*)d_in[8];
    const float* bk      = (const float*)d_in[9];
    const float* Wv      = (const float*)d_in[10];
    const float* bv      = (const float*)d_in[11];
    const float* Wo      = (const float*)d_in[12];
    const float* bo      = (const float*)d_in[13];
    const float* W1      = (const float*)d_in[14];
    const float* b1      = (const float*)d_in[15];
    const float* W2      = (const float*)d_in[16];
    const float* b2      = (const float*)d_in[17];
    const float* g1      = (const float*)d_in[18];
    const float* be1     = (const float*)d_in[19];
    const float* g2      = (const float*)d_in[20];
    const float* be2     = (const float*)d_in[21];
    const float* Wd1     = (const float*)d_in[22];
    const float* bd1     = (const float*)d_in[23];
    const float* Wd2     = (const float*)d_in[24];
    const float* bd2     = (const float*)d_in[25];
    const float* Wg      = (const float*)d_in[26];
    const float* ag      = (const float*)d_in[27];
    const float* Wgo     = (const float*)d_in[28];
    const float* ago     = (const float*)d_in[29];
    float* out = (float*)d_out;

    float *h, *q, *k, *v, *ao, *t, *ff;
    float *WqT, *WkT, *WvT, *WoT, *W1T, *W2T;
    cudaGetSymbolAddress((void**)&h,   g_h);
    cudaGetSymbolAddress((void**)&q,   g_q);
    cudaGetSymbolAddress((void**)&k,   g_k);
    cudaGetSymbolAddress((void**)&v,   g_v);
    cudaGetSymbolAddress((void**)&ao,  g_ao);
    cudaGetSymbolAddress((void**)&t,   g_t);
    cudaGetSymbolAddress((void**)&ff,  g_ff);
    cudaGetSymbolAddress((void**)&WqT, g_WqT);
    cudaGetSymbolAddress((void**)&WkT, g_WkT);
    cudaGetSymbolAddress((void**)&WvT, g_WvT);
    cudaGetSymbolAddress((void**)&WoT, g_WoT);
    cudaGetSymbolAddress((void**)&W1T, g_W1T);
    cudaGetSymbolAddress((void**)&W2T, g_W2T);

    cudaFuncSetAttribute(mma_gemm, cudaFuncAttributeMaxDynamicSharedMemorySize, MM_SMEM);
    cudaFuncSetAttribute(mma_gemm_qkv, cudaFuncAttributeMaxDynamicSharedMemorySize, MM_SMEM);

    // weight transposes (tf32-rounded), once per launch
    dim3 ttb(32, 8);
    transpose_tf32<<<dim3(DM / 32, DM / 32, NL), ttb>>>(Wq, WqT, DM, DM);
    transpose_tf32<<<dim3(DM / 32, DM / 32, NL), ttb>>>(Wk, WkT, DM, DM);
    transpose_tf32<<<dim3(DM / 32, DM / 32, NL), ttb>>>(Wv, WvT, DM, DM);
    transpose_tf32<<<dim3(DM / 32, DM / 32, NL), ttb>>>(Wo, WoT, DM, DM);
    transpose_tf32<<<dim3(DFF / 32, DM / 32, NL), ttb>>>(W1, W1T, DM, DFF);
    transpose_tf32<<<dim3(DM / 32, DFF / 32, NL), ttb>>>(W2, W2T, DFF, DM);

    gat_kernel<<<GAT_GRAPHS, 64>>>(x, adj, Wg, ag, Wgo, ago, out);
    enc_kernel<<<MROWS, 128>>>(x, W_enc, b_enc, cls_tok, pos_emb, h);

    int gy = (MROWS + 127) / 128;    // 41
    dim3 grid_qkv(DM / 128, gy, 3);
    dim3 grid_dm(DM / 128, gy);
    dim3 grid_ff(DFF / 128, gy);
    dim3 attn_grid((T + 63) / 64, NHEAD, NB);

    for (int l = 0; l < NL; l++) {
        mma_gemm_qkv<<<grid_qkv, 256, MM_SMEM>>>(
            h, WqT + (size_t)l * DM * DM, WkT + (size_t)l * DM * DM, WvT + (size_t)l * DM * DM,
            bq + l * DM, bk + l * DM, bv + l * DM, q, k, v);
        attn_kernel<<<attn_grid, 128>>>(q, k, v, ao);
        mma_gemm<<<grid_dm, 256, MM_SMEM>>>(ao, WoT + (size_t)l * DM * DM, bo + l * DM, t, MROWS, DM, DM, 0);
        add_ln_kernel<<<MROWS, 128>>>(h, t, g1 + l * DM, be1 + l * DM);
        mma_gemm<<<grid_ff, 256, MM_SMEM>>>(h, W1T + (size_t)l * DM * DFF, b1 + l * DFF, ff, MROWS, DFF, DM, 1);
        mma_gemm<<<grid_dm, 256, MM_SMEM>>>(ff, W2T + (size_t)l * DFF * DM, b2 + l * DM, t, MROWS, DM, DFF, 0);
        add_ln_kernel<<<MROWS, 128>>>(h, t, g2 + l * DM, be2 + l * DM);
    }

    head_kernel<<<1, 256>>>(h, Wd1, bd1, Wd2, bd2, out);
}

// round 5
// speedup vs baseline: 1.9497x; 1.1943x over previous
#include <cuda_runtime.h>
#include <cuda_bf16.h>
#include <math.h>
#include <stdint.h>

// ---------------- problem constants ----------------
#define NB 5
#define SEQ 1024
#define T 1025
#define DM 512
#define NHEAD 8
#define HD 64
#define DFF 2048
#define NL 4
#define NTOK 51
#define MLPD 256
#define CLASSES 7
#define GH 3
#define GHID 64
#define GCLS 5
#define MROWS (NB * T)
#define GAT_GRAPHS (SEQ * 5)
#define OUT_GAT_BASE (NB * CLASSES)

// ---------------- scratch ----------------
__device__ float g_h [MROWS * DM];
__device__ float g_q [MROWS * DM];
__device__ float g_k [MROWS * DM];
__device__ float g_v [MROWS * DM];
__device__ float g_ao[MROWS * DM];
__device__ float g_t [MROWS * DM];
__device__ float g_ff[MROWS * DFF];
// transposed (tf32-rounded) weights
__device__ float g_WqT[NL * DM * DM];
__device__ float g_WkT[NL * DM * DM];
__device__ float g_WvT[NL * DM * DM];
__device__ float g_WoT[NL * DM * DM];
__device__ float g_W1T[NL * DM * DFF];
__device__ float g_W2T[NL * DFF * DM];

// ---------------- helpers ----------------
__device__ __forceinline__ uint32_t ftf32(float x) {
    uint32_t r;
    asm("cvt.rna.tf32.f32 %0, %1;" : "=r"(r) : "f"(x));
    return r;
}

#define MMA_TF32(d, a, b) \
    asm volatile("mma.sync.aligned.m16n8k8.row.col.f32.tf32.tf32.f32 " \
        "{%0,%1,%2,%3}, {%4,%5,%6,%7}, {%8,%9}, {%0,%1,%2,%3};" \
        : "+f"((d)[0]), "+f"((d)[1]), "+f"((d)[2]), "+f"((d)[3]) \
        : "r"((a).x), "r"((a).y), "r"((a).z), "r"((a).w), \
          "r"((b).x), "r"((b).y))

#define MMA_TF32_P(d, a0, a1, a2, a3, b) \
    asm volatile("mma.sync.aligned.m16n8k8.row.col.f32.tf32.tf32.f32 " \
        "{%0,%1,%2,%3}, {%4,%5,%6,%7}, {%8,%9}, {%0,%1,%2,%3};" \
        : "+f"((d)[0]), "+f"((d)[1]), "+f"((d)[2]), "+f"((d)[3]) \
        : "r"(a0), "r"(a1), "r"(a2), "r"(a3), \
          "r"((b).x), "r"((b).y))

// ---------------- weight transpose + tf32 round: Wt[n][k] = tf32(W[k][n]) ----------------
__global__ void transpose_tf32(const float* __restrict__ W, float* __restrict__ Wt, int K, int N)
{
    __shared__ float t[32][33];
    const float* w = W + (size_t)blockIdx.z * K * N;
    float* o = Wt + (size_t)blockIdx.z * K * N;
    int n0 = blockIdx.x * 32, k0 = blockIdx.y * 32;
    int tx = threadIdx.x, ty = threadIdx.y;   // 32 x 8
    #pragma unroll
    for (int i = 0; i < 32; i += 8)
        t[ty + i][tx] = w[(size_t)(k0 + ty + i) * N + n0 + tx];
    __syncthreads();
    #pragma unroll
    for (int i = 0; i < 32; i += 8)
        o[(size_t)(n0 + ty + i) * K + k0 + tx] = __uint_as_float(ftf32(t[tx][ty + i]));
}

// ---------------- tf32 mma.sync GEMM (unchanged from round 4) ----------------
#define MM_SMEM 65536

__device__ __forceinline__ void mma_gemm_body(
    const float* __restrict__ A, const float* __restrict__ Bt,
    const float* __restrict__ bias, float* __restrict__ C,
    int M, int N, int K, int relu)
{
    extern __shared__ float sm[];
    int tid = threadIdx.x;
    int w = tid >> 5, lane = tid & 31;
    int bm = blockIdx.y * 128, bn = blockIdx.x * 128;
    int wm = (w & 1) * 64;
    int wn = (w >> 1) * 32;

    float d[4][4][4];
    #pragma unroll
    for (int i = 0; i < 4; i++)
        #pragma unroll
        for (int j = 0; j < 4; j++)
            #pragma unroll
            for (int e = 0; e < 4; e++) d[i][j][e] = 0.f;

    uint4 ra[4], rb[4];
    int nch = K >> 5;

    #pragma unroll
    for (int it = 0; it < 4; it++) {
        int idx = tid + it * 256;
        int r = idx >> 3, c4 = (idx & 7) << 2;
        float4 av = make_float4(0.f, 0.f, 0.f, 0.f);
        if (bm + r < M) av = *(const float4*)(A + (size_t)(bm + r) * K + c4);
        ra[it].x = ftf32(av.x); ra[it].y = ftf32(av.y);
        ra[it].z = ftf32(av.z); ra[it].w = ftf32(av.w);
        rb[it] = *(const uint4*)(Bt + (size_t)(bn + r) * K + c4);
    }
    {
        uint32_t* As = (uint32_t*)sm;
        uint32_t* Bs = (uint32_t*)sm + 8192;
        #pragma unroll
        for (int it = 0; it < 4; it++) {
            int idx = tid + it * 256;
            int r = idx >> 3, c4 = (idx & 7) << 2;
            int kt = c4 >> 3, kin0 = c4 & 7;
            int mt = r >> 4, rin = r & 15;
            int regA = (kin0 ? 2 : 0) + ((rin >> 3) & 1);
            uint32_t* dA = As + ((kt * 8 + mt) * 32 + (rin & 7) * 4) * 4 + regA;
            dA[0] = ra[it].x; dA[4] = ra[it].y; dA[8] = ra[it].z; dA[12] = ra[it].w;
            int nt = r >> 3, nin = r & 7;
            int regB = kin0 ? 1 : 0;
            uint32_t* dB = Bs + ((kt * 16 + nt) * 32 + nin * 4) * 2 + regB;
            dB[0] = rb[it].x; dB[2] = rb[it].y; dB[4] = rb[it].z; dB[6] = rb[it].w;
        }
    }
    __syncthreads();

    for (int c = 0; c < nch; c++) {
        int buf = c & 1;
        uint32_t* As = (uint32_t*)sm + buf * 4096;
        uint32_t* Bs = (uint32_t*)sm + 8192 + buf * 4096;

        if (c + 1 < nch) {
            int k0 = (c + 1) << 5;
            #pragma unroll
            for (int it = 0; it < 4; it++) {
                int idx = tid + it * 256;
                int r = idx >> 3, c4 = (idx & 7) << 2;
                float4 av = make_float4(0.f, 0.f, 0.f, 0.f);
                if (bm + r < M) av = *(const float4*)(A + (size_t)(bm + r) * K + k0 + c4);
                ra[it].x = ftf32(av.x); ra[it].y = ftf32(av.y);
                ra[it].z = ftf32(av.z); ra[it].w = ftf32(av.w);
                rb[it] = *(const uint4*)(Bt + (size_t)(bn + r) * K + k0 + c4);
            }
        }

        #pragma unroll
        for (int kt = 0; kt < 4; kt++) {
            uint4 af[4];
            uint2 bf[4];
            #pragma unroll
            for (int i = 0; i < 4; i++)
                af[i] = *(uint4*)(As + ((kt * 8 + (wm >> 4) + i) * 32 + lane) * 4);
            #pragma unroll
            for (int j = 0; j < 4; j++)
                bf[j] = *(uint2*)(Bs + ((kt * 16 + (wn >> 3) + j) * 32 + lane) * 2);
            #pragma unroll
            for (int i = 0; i < 4; i++)
                #pragma unroll
                for (int j = 0; j < 4; j++)
                    MMA_TF32(d[i][j], af[i], bf[j]);
        }
        __syncthreads();

        if (c + 1 < nch) {
            uint32_t* As2 = (uint32_t*)sm + (buf ^ 1) * 4096;
            uint32_t* Bs2 = (uint32_t*)sm + 8192 + (buf ^ 1) * 4096;
            #pragma unroll
            for (int it = 0; it < 4; it++) {
                int idx = tid + it * 256;
                int r = idx >> 3, c4 = (idx & 7) << 2;
                int kt = c4 >> 3, kin0 = c4 & 7;
                int mt = r >> 4, rin = r & 15;
                int regA = (kin0 ? 2 : 0) + ((rin >> 3) & 1);
                uint32_t* dA = As2 + ((kt * 8 + mt) * 32 + (rin & 7) * 4) * 4 + regA;
                dA[0] = ra[it].x; dA[4] = ra[it].y; dA[8] = ra[it].z; dA[12] = ra[it].w;
                int nt = r >> 3, nin = r & 7;
                int regB = kin0 ? 1 : 0;
                uint32_t* dB = Bs2 + ((kt * 16 + nt) * 32 + nin * 4) * 2 + regB;
                dB[0] = rb[it].x; dB[2] = rb[it].y; dB[4] = rb[it].z; dB[6] = rb[it].w;
            }
            __syncthreads();
        }
    }

    int g = lane >> 2, t2 = (lane & 3) << 1;
    #pragma unroll
    for (int i = 0; i < 4; i++) {
        #pragma unroll
        for (int hh = 0; hh < 2; hh++) {
            int row = bm + wm + i * 16 + g + hh * 8;
            if (row >= M) continue;
            #pragma unroll
            for (int j = 0; j < 4; j++) {
                int col = bn + wn + j * 8 + t2;
                float2 bb = *(const float2*)(bias + col);
                float2 r;
                r.x = d[i][j][hh * 2 + 0] + bb.x;
                r.y = d[i][j][hh * 2 + 1] + bb.y;
                if (relu) { r.x = fmaxf(r.x, 0.f); r.y = fmaxf(r.y, 0.f); }
                *(float2*)(C + (size_t)row * N + col) = r;
            }
        }
    }
}

__global__ __launch_bounds__(256) void mma_gemm(
    const float* __restrict__ A, const float* __restrict__ Bt,
    const float* __restrict__ bias, float* __restrict__ C,
    int M, int N, int K, int relu)
{
    mma_gemm_body(A, Bt, bias, C, M, N, K, relu);
}

__global__ __launch_bounds__(256) void mma_gemm_qkv(
    const float* __restrict__ A,
    const float* __restrict__ WqT, const float* __restrict__ WkT, const float* __restrict__ WvT,
    const float* __restrict__ bq, const float* __restrict__ bk, const float* __restrict__ bv,
    float* __restrict__ q, float* __restrict__ k, float* __restrict__ v)
{
    const float* Bt; const float* bias; float* C;
    if (blockIdx.z == 0)      { Bt = WqT; bias = bq; C = q; }
    else if (blockIdx.z == 1) { Bt = WkT; bias = bk; C = k; }
    else                      { Bt = WvT; bias = bv; C = v; }
    mma_gemm_body(A, Bt, bias, C, MROWS, DM, DM, 0);
}

// ---------------- tf32 mma.sync flash attention ----------------
// 64 q-rows per block (4 warps x 16), 64-key tiles, HD=64.
// Q fragments in registers, K/V staged fragment-major in SMEM.
// V split hi/lo (2 MMAs for PV) to cut tf32 rounding error.
__global__ __launch_bounds__(128) void attn_mma_kernel(
    const float* __restrict__ q, const float* __restrict__ k,
    const float* __restrict__ v, float* __restrict__ o)
{
    __shared__ float kp [4096];   // K B-frags, reused for P A-frags
    __shared__ float vhi[4096];   // V hi B-frags
    __shared__ float vlo[4096];   // V lo B-frags

    int tid = threadIdx.x;
    int w = tid >> 5, lane = tid & 31;
    int g = lane >> 2, t = lane & 3;
    int qb = blockIdx.x * 64;
    int head = blockIdx.y, b = blockIdx.z;
    const size_t bs = (size_t)T * DM;
    const float* qp = q + b * bs + head * HD;
    const float* kpg = k + b * bs + head * HD;
    const float* vpg = v + b * bs + head * HD;
    float* op = o + b * bs + head * HD;

    // ---- load Q fragments (held for whole kernel), scaled by 1/8 ----
    int r0 = qb + w * 16 + g;
    int r1 = r0 + 8;
    uint32_t aq[8][4];
    #pragma unroll
    for (int kk = 0; kk < 8; kk++) {
        int d0 = kk * 8 + t, d1 = d0 + 4;
        float q00 = 0.f, q01 = 0.f, q10 = 0.f, q11 = 0.f;
        if (r0 < T) { q00 = qp[(size_t)r0 * DM + d0]; q01 = qp[(size_t)r0 * DM + d1]; }
        if (r1 < T) { q10 = qp[(size_t)r1 * DM + d0]; q11 = qp[(size_t)r1 * DM + d1]; }
        aq[kk][0] = ftf32(q00 * 0.125f);
        aq[kk][1] = ftf32(q10 * 0.125f);
        aq[kk][2] = ftf32(q01 * 0.125f);
        aq[kk][3] = ftf32(q11 * 0.125f);
    }

    float oc[8][4];
    #pragma unroll
    for (int j = 0; j < 8; j++)
        #pragma unroll
        for (int e = 0; e < 4; e++) oc[j][e] = 0.f;
    float m0 = -1e30f, m1 = -1e30f, l0 = 0.f, l1 = 0.f;

    for (int kb = 0; kb < T; kb += 64) {
        __syncthreads();   // prev tile's PV done before overwriting buffers
        // ---- stage K and V (frag-major) ----
        for (int idx = tid; idx < 4096; idx += 128) {
            int key = idx >> 6, dd = idx & 63;
            int s = kb + key;
            float kv = 0.f, vv = 0.f;
            if (s < T) {
                kv = kpg[(size_t)s * DM + dd];
                vv = vpg[(size_t)s * DM + dd];
            }
            // K B-frag: k-index = d, n-index = key
            kp[((dd >> 3) * 8 + (key >> 3)) * 64 + ((key & 7) * 4 + (dd & 3)) * 2 + ((dd & 7) >> 2)]
                = __uint_as_float(ftf32(kv));
            // V B-frag: k-index = key, n-index = d ; split hi/lo
            uint32_t hb = ftf32(vv);
            float hf = __uint_as_float(hb);
            uint32_t lb = ftf32(vv - hf);
            int a2 = ((key >> 3) * 8 + (dd >> 3)) * 64 + ((dd & 7) * 4 + (key & 3)) * 2 + ((key & 7) >> 2);
            vhi[a2] = __uint_as_float(hb);
            vlo[a2] = __uint_as_float(lb);
        }
        __syncthreads();

        // ---- S = Q K^T ----
        float sc[8][4];
        #pragma unroll
        for (int j = 0; j < 8; j++)
            #pragma unroll
            for (int e = 0; e < 4; e++) sc[j][e] = 0.f;
        #pragma unroll
        for (int kk = 0; kk < 8; kk++) {
            #pragma unroll
            for (int j = 0; j < 8; j++) {
                uint2 bf = *(const uint2*)&kp[(kk * 8 + j) * 64 + lane * 2];
                MMA_TF32_P(sc[j], aq[kk][0], aq[kk][1], aq[kk][2], aq[kk][3], bf);
            }
        }
        __syncthreads();   // done reading K frags (kp will hold P next)

        // ---- mask + online softmax ----
        int rem = T - kb;
        if (rem < 64) {
            #pragma unroll
            for (int j = 0; j < 8; j++) {
                int c0 = j * 8 + t * 2, c1 = c0 + 1;
                if (c0 >= rem) { sc[j][0] = -1e30f; sc[j][2] = -1e30f; }
                if (c1 >= rem) { sc[j][1] = -1e30f; sc[j][3] = -1e30f; }
            }
        }
        float mx0 = -1e30f, mx1 = -1e30f;
        #pragma unroll
        for (int j = 0; j < 8; j++) {
            mx0 = fmaxf(mx0, fmaxf(sc[j][0], sc[j][1]));
            mx1 = fmaxf(mx1, fmaxf(sc[j][2], sc[j][3]));
        }
        mx0 = fmaxf(mx0, __shfl_xor_sync(0xffffffffu, mx0, 1));
        mx0 = fmaxf(mx0, __shfl_xor_sync(0xffffffffu, mx0, 2));
        mx1 = fmaxf(mx1, __shfl_xor_sync(0xffffffffu, mx1, 1));
        mx1 = fmaxf(mx1, __shfl_xor_sync(0xffffffffu, mx1, 2));
        float mn0 = fmaxf(m0, mx0), mn1 = fmaxf(m1, mx1);
        float corr0 = __expf(m0 - mn0), corr1 = __expf(m1 - mn1);
        m0 = mn0; m1 = mn1;
        float sum0 = 0.f, sum1 = 0.f;
        #pragma unroll
        for (int j = 0; j < 8; j++) {
            sc[j][0] = __expf(sc[j][0] - mn0); sum0 += sc[j][0];
            sc[j][1] = __expf(sc[j][1] - mn0); sum0 += sc[j][1];
            sc[j][2] = __expf(sc[j][2] - mn1); sum1 += sc[j][2];
            sc[j][3] = __expf(sc[j][3] - mn1); sum1 += sc[j][3];
        }
        sum0 += __shfl_xor_sync(0xffffffffu, sum0, 1);
        sum0 += __shfl_xor_sync(0xffffffffu, sum0, 2);
        sum1 += __shfl_xor_sync(0xffffffffu, sum1, 1);
        sum1 += __shfl_xor_sync(0xffffffffu, sum1, 2);
        l0 = l0 * corr0 + sum0;
        l1 = l1 * corr1 + sum1;
        #pragma unroll
        for (int j = 0; j < 8; j++) {
            oc[j][0] *= corr0; oc[j][1] *= corr0;
            oc[j][2] *= corr1; oc[j][3] *= corr1;
        }

        // ---- store P as A-fragments into kp (per-warp 16x64 stripe) ----
        {
            float* pb = kp + w * 1024;
            #pragma unroll
            for (int j = 0; j < 8; j++) {
                #pragma unroll
                for (int e = 0; e < 2; e++) {
                    int kcol = t * 2 + e;                 // col within 8-tile
                    int base = j * 128 + (g * 4 + (kcol & 3)) * 4 + ((kcol >= 4) ? 2 : 0);
                    pb[base + 0] = __uint_as_float(ftf32(sc[j][e]));       // row g
                    pb[base + 1] = __uint_as_float(ftf32(sc[j][2 + e]));   // row g+8
                }
            }
        }
        __syncthreads();

        // ---- O += P V (hi + lo) ----
        const float* pb = kp + w * 1024;
        #pragma unroll
        for (int kk = 0; kk < 8; kk++) {
            uint4 pf = *(const uint4*)&pb[kk * 128 + lane * 4];
            #pragma unroll
            for (int j = 0; j < 8; j++) {
                uint2 bh = *(const uint2*)&vhi[(kk * 8 + j) * 64 + lane * 2];
                MMA_TF32(oc[j], pf, bh);
                uint2 bl = *(const uint2*)&vlo[(kk * 8 + j) * 64 + lane * 2];
                MMA_TF32(oc[j], pf, bl);
            }
        }
    }

    // ---- epilogue ----
    float inv0 = 1.f / l0, inv1 = 1.f / l1;
    #pragma unroll
    for (int j = 0; j < 8; j++) {
        int c0 = j * 8 + t * 2;
        if (r0 < T) {
            float2 rr = make_float2(oc[j][0] * inv0, oc[j][1] * inv0);
            *(float2*)(op + (size_t)r0 * DM + c0) = rr;
        }
        if (r1 < T) {
            float2 rr = make_float2(oc[j][2] * inv1, oc[j][3] * inv1);
            *(float2*)(op + (size_t)r1 * DM + c0) = rr;
        }
    }
}

// ---------------- encoder ----------------
__global__ void enc_kernel(const float* __restrict__ x,
                           const float* __restrict__ W_enc,
                           const float* __restrict__ b_enc,
                           const float* __restrict__ cls_tok,
                           const float* __restrict__ pos_emb,
                           float* __restrict__ h)
{
    int row = blockIdx.x;
    int b = row / T, t = row % T;
    int tid = threadIdx.x;           // 128
    float* hr = h + (size_t)row * DM;
    if (t == 0) {
        for (int d = tid; d < DM; d += 128)
            hr[d] = cls_tok[d] + pos_emb[d];
        return;
    }
    __shared__ float xs[NTOK];
    if (tid < NTOK) xs[tid] = x[(size_t)b * SEQ * NTOK + (size_t)(t - 1) * NTOK + tid];
    __syncthreads();
    for (int d = tid; d < DM; d += 128) {
        float acc = b_enc[d] + pos_emb[(size_t)t * DM + d];
        #pragma unroll 17
        for (int kk = 0; kk < NTOK; kk++)
            acc += xs[kk] * W_enc[kk * DM + d];
        hr[d] = acc;
    }
}

// ---------------- residual add + layernorm ----------------
__global__ void add_ln_kernel(float* __restrict__ h, const float* __restrict__ f,
                              const float* __restrict__ gamma, const float* __restrict__ beta)
{
    int row = blockIdx.x;
    int tid = threadIdx.x;  // 128
    float* hr = h + (size_t)row * DM;
    const float* fr = f + (size_t)row * DM;
    float v[4];
    float s = 0.f;
    #pragma unroll
    for (int i = 0; i < 4; i++) {
        v[i] = hr[tid + 128 * i] + fr[tid + 128 * i];
        s += v[i];
    }
    __shared__ float sm2[4];
    int lane = tid & 31, warp = tid >> 5;
    #pragma unroll
    for (int off = 16; off >= 1; off >>= 1) s += __shfl_xor_sync(0xffffffffu, s, off);
    if (lane == 0) sm2[warp] = s;
    __syncthreads();
    float mean = (sm2[0] + sm2[1] + sm2[2] + sm2[3]) * (1.f / DM);
    float vs = 0.f;
    #pragma unroll
    for (int i = 0; i < 4; i++) { float d = v[i] - mean; vs += d * d; }
    __syncthreads();
    #pragma unroll
    for (int off = 16; off >= 1; off >>= 1) vs += __shfl_xor_sync(0xffffffffu, vs, off);
    if (lane == 0) sm2[warp] = vs;
    __syncthreads();
    float var = (sm2[0] + sm2[1] + sm2[2] + sm2[3]) * (1.f / DM);
    float inv = rsqrtf(var + 1e-5f);
    #pragma unroll
    for (int i = 0; i < 4; i++) {
        int d = tid + 128 * i;
        hr[d] = (v[i] - mean) * inv * gamma[d] + beta[d];
    }
}

// ---------------- classification head ----------------
__global__ void head_kernel(const float* __restrict__ h,
                            const float* __restrict__ Wd1, const float* __restrict__ bd1,
                            const float* __restrict__ Wd2, const float* __restrict__ bd2,
                            float* __restrict__ out)
{
    __shared__ float mid[NB][MLPD];
    int tid = threadIdx.x; // 256
    for (int b = 0; b < NB; b++) {
        const float* cls = h + (size_t)b * T * DM;
        float acc = bd1[tid];
        for (int kk = 0; kk < DM; kk++)
            acc += cls[kk] * Wd1[kk * MLPD + tid];
        mid[b][tid] = acc;
    }
    __syncthreads();
    if (tid < NB * CLASSES) {
        int b = tid / CLASSES, c = tid % CLASSES;
        float acc = bd2[c];
        for (int m = 0; m < MLPD; m++)
            acc += mid[b][m] * Wd2[m * CLASSES + c];
        out[b * CLASSES + c] = acc;
    }
}

// ---------------- GAT branch ----------------
__global__ __launch_bounds__(64) void gat_kernel(
    const float* __restrict__ x, const int* __restrict__ adj,
    const float* __restrict__ Wg, const float* __restrict__ ag,
    const float* __restrict__ Wgo, const float* __restrict__ ago,
    float* __restrict__ out)
{
    int gidx = blockIdx.x;
    int s = gidx / 5, g = gidx % 5;
    int tid = threadIdx.x;
    int lane = tid & 31, warp = tid >> 5;

    __shared__ float xg[5][3];
    __shared__ float hcat[5][GH * GHID];
    __shared__ float att[5][5];
    __shared__ float s1[5], s2[5];
    __shared__ float red[2][5][2];
    __shared__ int msk[25];
    __shared__ float h2[5][5];
    __shared__ float o2[5][5];

    if (tid < 15) {
        int n = tid / 3, c = tid % 3;
        xg[n][c] = x[(size_t)n * SEQ * NTOK + (size_t)s * NTOK + g * 3 + c];
    }
    if (tid < 25) msk[tid] = adj[tid];
    __syncthreads();

    for (int head = 0; head < GH; head++) {
        const float* W = Wg + head * 3 * GHID;
        float hval[5];
        #pragma unroll
        for (int n = 0; n < 5; n++)
            hval[n] = xg[n][0] * W[tid] + xg[n][1] * W[GHID + tid] + xg[n][2] * W[2 * GHID + tid];
        float a1 = ag[head * 2 * GHID + tid];
        float a2 = ag[head * 2 * GHID + GHID + tid];
        #pragma unroll
        for (int n = 0; n < 5; n++) {
            float p1 = hval[n] * a1, p2 = hval[n] * a2;
            #pragma unroll
            for (int off = 16; off >= 1; off >>= 1) {
                p1 += __shfl_xor_sync(0xffffffffu, p1, off);
                p2 += __shfl_xor_sync(0xffffffffu, p2, off);
            }
            if (lane == 0) { red[warp][n][0] = p1; red[warp][n][1] = p2; }
        }
        __syncthreads();
        if (tid < 5) {
            s1[tid] = red[0][tid][0] + red[1][tid][0];
            s2[tid] = red[0][tid][1] + red[1][tid][1];
        }
        __syncthreads();
        if (tid < 5) {
            int i = tid;
            float ev[5]; float mx = -1e30f;
            #pragma unroll
            for (int j = 0; j < 5; j++) {
                if (msk[i * 5 + j]) {
                    float e = s1[i] + s2[j];
                    e = e > 0.f ? e : 0.2f * e;
                    ev[j] = e;
                    if (e > mx) mx = e;
                } else ev[j] = -1e30f;
            }
            float sum = 0.f;
            #pragma unroll
            for (int j = 0; j < 5; j++) {
                float p = msk[i * 5 + j] ? __expf(ev[j] - mx) : 0.f;
                att[i][j] = p; sum += p;
            }
            float invs = 1.f / sum;
            #pragma unroll
            for (int j = 0; j < 5; j++) att[i][j] *= invs;
        }
        __syncthreads();
        #pragma unroll
        for (int n = 0; n < 5; n++) {
            float o = att[n][0] * hval[0] + att[n][1] * hval[1] + att[n][2] * hval[2]
                    + att[n][3] * hval[3] + att[n][4] * hval[4];
            o = o > 0.f ? o : expm1f(o);
            hcat[n][head * GHID + tid] = o;
        }
        __syncthreads();
    }

    if (tid < 25) {
        int n = tid / 5, m = tid % 5;
        float acc = 0.f;
        for (int kk = 0; kk < GH * GHID; kk++)
            acc += hcat[n][kk] * Wgo[kk * GCLS + m];
        h2[n][m] = acc;
    }
    __syncthreads();
    if (tid < 5) {
        float a1 = 0.f, a2 = 0.f;
        #pragma unroll
        for (int m = 0; m < 5; m++) {
            a1 += h2[tid][m] * ago[m];
            a2 += h2[tid][m] * ago[GCLS + m];
        }
        s1[tid] = a1; s2[tid] = a2;
    }
    __syncthreads();
    if (tid < 5) {
        int i = tid;
        float ev[5]; float mx = -1e30f;
        #pragma unroll
        for (int j = 0; j < 5; j++) {
            if (msk[i * 5 + j]) {
                float e = s1[i] + s2[j];
                e = e > 0.f ? e : 0.2f * e;
                ev[j] = e;
                if (e > mx) mx = e;
            } else ev[j] = -1e30f;
        }
        float sum = 0.f;
        #pragma unroll
        for (int j = 0; j < 5; j++) {
            float p = msk[i * 5 + j] ? __expf(ev[j] - mx) : 0.f;
            att[i][j] = p; sum += p;
        }
        float invs = 1.f / sum;
        #pragma unroll
        for (int j = 0; j < 5; j++) att[i][j] *= invs;
    }
    __syncthreads();
    if (tid < 25) {
        int n = tid / 5, m = tid % 5;
        float o = 0.f;
        #pragma unroll
        for (int j = 0; j < 5; j++) o += att[n][j] * h2[j][m];
        o = o > 0.f ? o : expm1f(o);
        o2[n][m] = o;
    }
    __syncthreads();
    if (tid < 5) {
        int n = tid;
        float mx = -1e30f;
        #pragma unroll
        for (int m = 0; m < 5; m++) mx = fmaxf(mx, o2[n][m]);
        float sum = 0.f;
        #pragma unroll
        for (int m = 0; m < 5; m++) sum += __expf(o2[n][m] - mx);
        float lse = mx + logf(sum);
        #pragma unroll
        for (int m = 0; m < 5; m++)
            out[OUT_GAT_BASE + (size_t)gidx * 25 + n * 5 + m] = o2[n][m] - lse;
    }
}

// ---------------- host orchestration ----------------
extern "C" void kernel_launch(void* const* d_in, const int* in_sizes, int n_in,
                              void* d_out, int out_size)
{
    const float* x       = (const float*)d_in[0];
    const int*   adj     = (const int*)  d_in[1];
    const float* W_enc   = (const float*)d_in[2];
    const float* b_enc   = (const float*)d_in[3];
    const float* cls_tok = (const float*)d_in[4];
    const float* pos_emb = (const float*)d_in[5];
    const float* Wq      = (const float*)d_in[6];
    const float* bq      = (const float*)d_in[7];
    const float* Wk      = (const float*)d_in[8];
    const float* bk      = (const float*)d_in[9];
    const float* Wv      = (const float*)d_in[10];
    const float* bv      = (const float*)d_in[11];
    const float* Wo      = (const float*)d_in[12];
    const float* bo      = (const float*)d_in[13];
    const float* W1      = (const float*)d_in[14];
    const float* b1      = (const float*)d_in[15];
    const float* W2      = (const float*)d_in[16];
    const float* b2      = (const float*)d_in[17];
    const float* g1      = (const float*)d_in[18];
    const float* be1     = (const float*)d_in[19];
    const float* g2      = (const float*)d_in[20];
    const float* be2     = (const float*)d_in[21];
    const float* Wd1     = (const float*)d_in[22];
    const float* bd1     = (const float*)d_in[23];
    const float* Wd2     = (const float*)d_in[24];
    const float* bd2     = (const float*)d_in[25];
    const float* Wg      = (const float*)d_in[26];
    const float* ag      = (const float*)d_in[27];
    const float* Wgo     = (const float*)d_in[28];
    const float* ago     = (const float*)d_in[29];
    float* out = (float*)d_out;

    float *h, *q, *k, *v, *ao, *t, *ff;
    float *WqT, *WkT, *WvT, *WoT, *W1T, *W2T;
    cudaGetSymbolAddress((void**)&h,   g_h);
    cudaGetSymbolAddress((void**)&q,   g_q);
    cudaGetSymbolAddress((void**)&k,   g_k);
    cudaGetSymbolAddress((void**)&v,   g_v);
    cudaGetSymbolAddress((void**)&ao,  g_ao);
    cudaGetSymbolAddress((void**)&t,   g_t);
    cudaGetSymbolAddress((void**)&ff,  g_ff);
    cudaGetSymbolAddress((void**)&WqT, g_WqT);
    cudaGetSymbolAddress((void**)&WkT, g_WkT);
    cudaGetSymbolAddress((void**)&WvT, g_WvT);
    cudaGetSymbolAddress((void**)&WoT, g_WoT);
    cudaGetSymbolAddress((void**)&W1T, g_W1T);
    cudaGetSymbolAddress((void**)&W2T, g_W2T);

    cudaFuncSetAttribute(mma_gemm, cudaFuncAttributeMaxDynamicSharedMemorySize, MM_SMEM);
    cudaFuncSetAttribute(mma_gemm_qkv, cudaFuncAttributeMaxDynamicSharedMemorySize, MM_SMEM);

    // weight transposes (tf32-rounded), once per launch
    dim3 ttb(32, 8);
    transpose_tf32<<<dim3(DM / 32, DM / 32, NL), ttb>>>(Wq, WqT, DM, DM);
    transpose_tf32<<<dim3(DM / 32, DM / 32, NL), ttb>>>(Wk, WkT, DM, DM);
    transpose_tf32<<<dim3(DM / 32, DM / 32, NL), ttb>>>(Wv, WvT, DM, DM);
    transpose_tf32<<<dim3(DM / 32, DM / 32, NL), ttb>>>(Wo, WoT, DM, DM);
    transpose_tf32<<<dim3(DFF / 32, DM / 32, NL), ttb>>>(W1, W1T, DM, DFF);
    transpose_tf32<<<dim3(DM / 32, DFF / 32, NL), ttb>>>(W2, W2T, DFF, DM);

    gat_kernel<<<GAT_GRAPHS, 64>>>(x, adj, Wg, ag, Wgo, ago, out);
    enc_kernel<<<MROWS, 128>>>(x, W_enc, b_enc, cls_tok, pos_emb, h);

    int gy = (MROWS + 127) / 128;    // 41
    dim3 grid_qkv(DM / 128, gy, 3);
    dim3 grid_dm(DM / 128, gy);
    dim3 grid_ff(DFF / 128, gy);
    dim3 attn_grid((T + 63) / 64, NHEAD, NB);

    for (int l = 0; l < NL; l++) {
        mma_gemm_qkv<<<grid_qkv, 256, MM_SMEM>>>(
            h, WqT + (size_t)l * DM * DM, WkT + (size_t)l * DM * DM, WvT + (size_t)l * DM * DM,
            bq + l * DM, bk + l * DM, bv + l * DM, q, k, v);
        attn_mma_kernel<<<attn_grid, 128>>>(q, k, v, ao);
        mma_gemm<<<grid_dm, 256, MM_SMEM>>>(ao, WoT + (size_t)l * DM * DM, bo + l * DM, t, MROWS, DM, DM, 0);
        add_ln_kernel<<<MROWS, 128>>>(h, t, g1 + l * DM, be1 + l * DM);
        mma_gemm<<<grid_ff, 256, MM_SMEM>>>(h, W1T + (size_t)l * DM * DFF, b1 + l * DFF, ff, MROWS, DFF, DM, 1);
        mma_gemm<<<grid_dm, 256, MM_SMEM>>>(ff, W2T + (size_t)l * DFF * DM, b2 + l * DM, t, MROWS, DM, DFF, 0);
        add_ln_kernel<<<MROWS, 128>>>(h, t, g2 + l * DM, be2 + l * DM);
    }

    head_kernel<<<1, 256>>>(h, Wd1, bd1, Wd2, bd2, out);
}

// round 6
// speedup vs baseline: 2.0244x; 1.0383x over previous
#include <cuda_runtime.h>
#include <cuda_bf16.h>
#include <math.h>
#include <stdint.h>

// ---------------- problem constants ----------------
#define NB 5
#define SEQ 1024
#define T 1025
#define DM 512
#define NHEAD 8
#define HD 64
#define DFF 2048
#define NL 4
#define NTOK 51
#define MLPD 256
#define CLASSES 7
#define GH 3
#define GHID 64
#define GCLS 5
#define MROWS (NB * T)
#define GAT_GRAPHS (SEQ * 5)
#define OUT_GAT_BASE (NB * CLASSES)

// ---------------- scratch ----------------
__device__ float g_h [MROWS * DM];
__device__ float g_q [MROWS * DM];
__device__ float g_k [MROWS * DM];
__device__ float g_v [MROWS * DM];
__device__ float g_ao[MROWS * DM];
__device__ float g_t [MROWS * DM];
__device__ float g_ff[MROWS * DFF];
// transposed (tf32-rounded) weights
__device__ float g_WqT[NL * DM * DM];
__device__ float g_WkT[NL * DM * DM];
__device__ float g_WvT[NL * DM * DM];
__device__ float g_WoT[NL * DM * DM];
__device__ float g_W1T[NL * DM * DFF];
__device__ float g_W2T[NL * DFF * DM];

// ---------------- helpers ----------------
__device__ __forceinline__ uint32_t ftf32(float x) {
    uint32_t r;
    asm("cvt.rna.tf32.f32 %0, %1;" : "=r"(r) : "f"(x));
    return r;
}

#define MMA_TF32(d, a, b) \
    asm volatile("mma.sync.aligned.m16n8k8.row.col.f32.tf32.tf32.f32 " \
        "{%0,%1,%2,%3}, {%4,%5,%6,%7}, {%8,%9}, {%0,%1,%2,%3};" \
        : "+f"((d)[0]), "+f"((d)[1]), "+f"((d)[2]), "+f"((d)[3]) \
        : "r"((a).x), "r"((a).y), "r"((a).z), "r"((a).w), \
          "r"((b).x), "r"((b).y))

#define MMA_TF32_P(d, a0, a1, a2, a3, b) \
    asm volatile("mma.sync.aligned.m16n8k8.row.col.f32.tf32.tf32.f32 " \
        "{%0,%1,%2,%3}, {%4,%5,%6,%7}, {%8,%9}, {%0,%1,%2,%3};" \
        : "+f"((d)[0]), "+f"((d)[1]), "+f"((d)[2]), "+f"((d)[3]) \
        : "r"(a0), "r"(a1), "r"(a2), "r"(a3), \
          "r"((b).x), "r"((b).y))

// ---------------- all weight transposes in one launch ----------------
// jobs: 0..3 = Wq,Wk,Wv,Wo (512x512, 1024 blocks each);
//       4 = W1 (512x2048, 4096 blocks); 5 = W2 (2048x512, 4096 blocks)
__global__ __launch_bounds__(256) void transpose_all(
    const float* __restrict__ Wq, const float* __restrict__ Wk,
    const float* __restrict__ Wv, const float* __restrict__ Wo,
    const float* __restrict__ W1, const float* __restrict__ W2,
    float* __restrict__ WqT, float* __restrict__ WkT,
    float* __restrict__ WvT, float* __restrict__ WoT,
    float* __restrict__ W1T, float* __restrict__ W2T)
{
    __shared__ float t[32][33];
    int bid = blockIdx.x;
    const float* W; float* Wt; int K, N, rel, nx;
    if (bid < 4096) {
        int job = bid >> 10; rel = bid & 1023;
        K = DM; N = DM; nx = 16;
        if (job == 0)      { W = Wq; Wt = WqT; }
        else if (job == 1) { W = Wk; Wt = WkT; }
        else if (job == 2) { W = Wv; Wt = WvT; }
        else               { W = Wo; Wt = WoT; }
    } else if (bid < 8192) {
        rel = bid - 4096; K = DM; N = DFF; nx = 64;
        W = W1; Wt = W1T;
    } else {
        rel = bid - 8192; K = DFF; N = DM; nx = 16;
        W = W2; Wt = W2T;
    }
    int ny = K >> 5;
    int per = nx * ny;
    int l = rel / per, r2 = rel % per;
    int n0 = (r2 % nx) * 32, k0 = (r2 / nx) * 32;
    const float* w = W + (size_t)l * K * N;
    float* o = Wt + (size_t)l * K * N;
    int tx = threadIdx.x & 31, ty = threadIdx.x >> 5;   // 32 x 8
    #pragma unroll
    for (int i = 0; i < 32; i += 8)
        t[ty + i][tx] = w[(size_t)(k0 + ty + i) * N + n0 + tx];
    __syncthreads();
    #pragma unroll
    for (int i = 0; i < 32; i += 8)
        o[(size_t)(n0 + ty + i) * K + k0 + tx] = __uint_as_float(ftf32(t[tx][ty + i]));
}

// ---------------- tf32 mma.sync GEMM (validated round 4/5) ----------------
#define MM_SMEM 65536

__device__ __forceinline__ void mma_gemm_body(
    const float* __restrict__ A, const float* __restrict__ Bt,
    const float* __restrict__ bias, float* __restrict__ C,
    int M, int N, int K, int relu)
{
    extern __shared__ float sm[];
    int tid = threadIdx.x;
    int w = tid >> 5, lane = tid & 31;
    int bm = blockIdx.y * 128, bn = blockIdx.x * 128;
    int wm = (w & 1) * 64;
    int wn = (w >> 1) * 32;

    float d[4][4][4];
    #pragma unroll
    for (int i = 0; i < 4; i++)
        #pragma unroll
        for (int j = 0; j < 4; j++)
            #pragma unroll
            for (int e = 0; e < 4; e++) d[i][j][e] = 0.f;

    uint4 ra[4], rb[4];
    int nch = K >> 5;

    #pragma unroll
    for (int it = 0; it < 4; it++) {
        int idx = tid + it * 256;
        int r = idx >> 3, c4 = (idx & 7) << 2;
        float4 av = make_float4(0.f, 0.f, 0.f, 0.f);
        if (bm + r < M) av = *(const float4*)(A + (size_t)(bm + r) * K + c4);
        ra[it].x = ftf32(av.x); ra[it].y = ftf32(av.y);
        ra[it].z = ftf32(av.z); ra[it].w = ftf32(av.w);
        rb[it] = *(const uint4*)(Bt + (size_t)(bn + r) * K + c4);
    }
    {
        uint32_t* As = (uint32_t*)sm;
        uint32_t* Bs = (uint32_t*)sm + 8192;
        #pragma unroll
        for (int it = 0; it < 4; it++) {
            int idx = tid + it * 256;
            int r = idx >> 3, c4 = (idx & 7) << 2;
            int kt = c4 >> 3, kin0 = c4 & 7;
            int mt = r >> 4, rin = r & 15;
            int regA = (kin0 ? 2 : 0) + ((rin >> 3) & 1);
            uint32_t* dA = As + ((kt * 8 + mt) * 32 + (rin & 7) * 4) * 4 + regA;
            dA[0] = ra[it].x; dA[4] = ra[it].y; dA[8] = ra[it].z; dA[12] = ra[it].w;
            int nt = r >> 3, nin = r & 7;
            int regB = kin0 ? 1 : 0;
            uint32_t* dB = Bs + ((kt * 16 + nt) * 32 + nin * 4) * 2 + regB;
            dB[0] = rb[it].x; dB[2] = rb[it].y; dB[4] = rb[it].z; dB[6] = rb[it].w;
        }
    }
    __syncthreads();

    for (int c = 0; c < nch; c++) {
        int buf = c & 1;
        uint32_t* As = (uint32_t*)sm + buf * 4096;
        uint32_t* Bs = (uint32_t*)sm + 8192 + buf * 4096;

        if (c + 1 < nch) {
            int k0 = (c + 1) << 5;
            #pragma unroll
            for (int it = 0; it < 4; it++) {
                int idx = tid + it * 256;
                int r = idx >> 3, c4 = (idx & 7) << 2;
                float4 av = make_float4(0.f, 0.f, 0.f, 0.f);
                if (bm + r < M) av = *(const float4*)(A + (size_t)(bm + r) * K + k0 + c4);
                ra[it].x = ftf32(av.x); ra[it].y = ftf32(av.y);
                ra[it].z = ftf32(av.z); ra[it].w = ftf32(av.w);
                rb[it] = *(const uint4*)(Bt + (size_t)(bn + r) * K + k0 + c4);
            }
        }

        #pragma unroll
        for (int kt = 0; kt < 4; kt++) {
            uint4 af[4];
            uint2 bf[4];
            #pragma unroll
            for (int i = 0; i < 4; i++)
                af[i] = *(uint4*)(As + ((kt * 8 + (wm >> 4) + i) * 32 + lane) * 4);
            #pragma unroll
            for (int j = 0; j < 4; j++)
                bf[j] = *(uint2*)(Bs + ((kt * 16 + (wn >> 3) + j) * 32 + lane) * 2);
            #pragma unroll
            for (int i = 0; i < 4; i++)
                #pragma unroll
                for (int j = 0; j < 4; j++)
                    MMA_TF32(d[i][j], af[i], bf[j]);
        }
        __syncthreads();

        if (c + 1 < nch) {
            uint32_t* As2 = (uint32_t*)sm + (buf ^ 1) * 4096;
            uint32_t* Bs2 = (uint32_t*)sm + 8192 + (buf ^ 1) * 4096;
            #pragma unroll
            for (int it = 0; it < 4; it++) {
                int idx = tid + it * 256;
                int r = idx >> 3, c4 = (idx & 7) << 2;
                int kt = c4 >> 3, kin0 = c4 & 7;
                int mt = r >> 4, rin = r & 15;
                int regA = (kin0 ? 2 : 0) + ((rin >> 3) & 1);
                uint32_t* dA = As2 + ((kt * 8 + mt) * 32 + (rin & 7) * 4) * 4 + regA;
                dA[0] = ra[it].x; dA[4] = ra[it].y; dA[8] = ra[it].z; dA[12] = ra[it].w;
                int nt = r >> 3, nin = r & 7;
                int regB = kin0 ? 1 : 0;
                uint32_t* dB = Bs2 + ((kt * 16 + nt) * 32 + nin * 4) * 2 + regB;
                dB[0] = rb[it].x; dB[2] = rb[it].y; dB[4] = rb[it].z; dB[6] = rb[it].w;
            }
            __syncthreads();
        }
    }

    int g = lane >> 2, t2 = (lane & 3) << 1;
    #pragma unroll
    for (int i = 0; i < 4; i++) {
        #pragma unroll
        for (int hh = 0; hh < 2; hh++) {
            int row = bm + wm + i * 16 + g + hh * 8;
            if (row >= M) continue;
            #pragma unroll
            for (int j = 0; j < 4; j++) {
                int col = bn + wn + j * 8 + t2;
                float2 bb = *(const float2*)(bias + col);
                float2 r;
                r.x = d[i][j][hh * 2 + 0] + bb.x;
                r.y = d[i][j][hh * 2 + 1] + bb.y;
                if (relu) { r.x = fmaxf(r.x, 0.f); r.y = fmaxf(r.y, 0.f); }
                *(float2*)(C + (size_t)row * N + col) = r;
            }
        }
    }
}

__global__ __launch_bounds__(256) void mma_gemm(
    const float* __restrict__ A, const float* __restrict__ Bt,
    const float* __restrict__ bias, float* __restrict__ C,
    int M, int N, int K, int relu)
{
    mma_gemm_body(A, Bt, bias, C, M, N, K, relu);
}

__global__ __launch_bounds__(256) void mma_gemm_qkv(
    const float* __restrict__ A,
    const float* __restrict__ WqT, const float* __restrict__ WkT, const float* __restrict__ WvT,
    const float* __restrict__ bq, const float* __restrict__ bk, const float* __restrict__ bv,
    float* __restrict__ q, float* __restrict__ k, float* __restrict__ v)
{
    const float* Bt; const float* bias; float* C;
    if (blockIdx.z == 0)      { Bt = WqT; bias = bq; C = q; }
    else if (blockIdx.z == 1) { Bt = WkT; bias = bk; C = k; }
    else                      { Bt = WvT; bias = bv; C = v; }
    mma_gemm_body(A, Bt, bias, C, MROWS, DM, DM, 0);
}

// ---------------- tf32 mma.sync flash attention, 128-row q-tile ----------------
// 128 q-rows per block (8 warps x 16 rows), 64-key tiles, HD=64.
// Q fragments in registers, K/V staged fragment-major in SMEM (dynamic 64KB).
// V split hi/lo (2 MMAs for PV) to cut tf32 rounding error.
#define ATT_SMEM 65536

__global__ __launch_bounds__(256) void attn_mma_kernel(
    const float* __restrict__ q, const float* __restrict__ k,
    const float* __restrict__ v, float* __restrict__ o)
{
    extern __shared__ float as_[];
    float* kp  = as_;            // 8192 floats: K B-frags (first 4096), then P A-frags
    float* vhi = as_ + 8192;     // 4096
    float* vlo = as_ + 12288;    // 4096

    int tid = threadIdx.x;
    int w = tid >> 5, lane = tid & 31;
    int g = lane >> 2, t = lane & 3;
    int qb = blockIdx.x * 128;
    int head = blockIdx.y, b = blockIdx.z;
    const size_t bs = (size_t)T * DM;
    const float* qp = q + b * bs + head * HD;
    const float* kpg = k + b * bs + head * HD;
    const float* vpg = v + b * bs + head * HD;
    float* op = o + b * bs + head * HD;

    // ---- load Q fragments (held for whole kernel), scaled by 1/8 ----
    int r0 = qb + w * 16 + g;
    int r1 = r0 + 8;
    uint32_t aq[8][4];
    #pragma unroll
    for (int kk = 0; kk < 8; kk++) {
        int d0 = kk * 8 + t, d1 = d0 + 4;
        float q00 = 0.f, q01 = 0.f, q10 = 0.f, q11 = 0.f;
        if (r0 < T) { q00 = qp[(size_t)r0 * DM + d0]; q01 = qp[(size_t)r0 * DM + d1]; }
        if (r1 < T) { q10 = qp[(size_t)r1 * DM + d0]; q11 = qp[(size_t)r1 * DM + d1]; }
        aq[kk][0] = ftf32(q00 * 0.125f);
        aq[kk][1] = ftf32(q10 * 0.125f);
        aq[kk][2] = ftf32(q01 * 0.125f);
        aq[kk][3] = ftf32(q11 * 0.125f);
    }

    float oc[8][4];
    #pragma unroll
    for (int j = 0; j < 8; j++)
        #pragma unroll
        for (int e = 0; e < 4; e++) oc[j][e] = 0.f;
    float m0 = -1e30f, m1 = -1e30f, l0 = 0.f, l1 = 0.f;

    for (int kb = 0; kb < T; kb += 64) {
        __syncthreads();   // prev tile's PV done before overwriting buffers
        // ---- stage K and V (frag-major) ----
        for (int idx = tid; idx < 4096; idx += 256) {
            int key = idx >> 6, dd = idx & 63;
            int s = kb + key;
            float kv = 0.f, vv = 0.f;
            if (s < T) {
                kv = kpg[(size_t)s * DM + dd];
                vv = vpg[(size_t)s * DM + dd];
            }
            // K B-frag: k-index = d, n-index = key
            kp[((dd >> 3) * 8 + (key >> 3)) * 64 + ((key & 7) * 4 + (dd & 3)) * 2 + ((dd & 7) >> 2)]
                = __uint_as_float(ftf32(kv));
            // V B-frag: k-index = key, n-index = d ; split hi/lo
            uint32_t hb = ftf32(vv);
            float hf = __uint_as_float(hb);
            uint32_t lb = ftf32(vv - hf);
            int a2 = ((key >> 3) * 8 + (dd >> 3)) * 64 + ((dd & 7) * 4 + (key & 3)) * 2 + ((key & 7) >> 2);
            vhi[a2] = __uint_as_float(hb);
            vlo[a2] = __uint_as_float(lb);
        }
        __syncthreads();

        // ---- S = Q K^T ----
        float sc[8][4];
        #pragma unroll
        for (int j = 0; j < 8; j++)
            #pragma unroll
            for (int e = 0; e < 4; e++) sc[j][e] = 0.f;
        #pragma unroll
        for (int kk = 0; kk < 8; kk++) {
            #pragma unroll
            for (int j = 0; j < 8; j++) {
                uint2 bf = *(const uint2*)&kp[(kk * 8 + j) * 64 + lane * 2];
                MMA_TF32_P(sc[j], aq[kk][0], aq[kk][1], aq[kk][2], aq[kk][3], bf);
            }
        }
        __syncthreads();   // done reading K frags (kp will hold P next)

        // ---- mask + online softmax ----
        int rem = T - kb;
        if (rem < 64) {
            #pragma unroll
            for (int j = 0; j < 8; j++) {
                int c0 = j * 8 + t * 2, c1 = c0 + 1;
                if (c0 >= rem) { sc[j][0] = -1e30f; sc[j][2] = -1e30f; }
                if (c1 >= rem) { sc[j][1] = -1e30f; sc[j][3] = -1e30f; }
            }
        }
        float mx0 = -1e30f, mx1 = -1e30f;
        #pragma unroll
        for (int j = 0; j < 8; j++) {
            mx0 = fmaxf(mx0, fmaxf(sc[j][0], sc[j][1]));
            mx1 = fmaxf(mx1, fmaxf(sc[j][2], sc[j][3]));
        }
        mx0 = fmaxf(mx0, __shfl_xor_sync(0xffffffffu, mx0, 1));
        mx0 = fmaxf(mx0, __shfl_xor_sync(0xffffffffu, mx0, 2));
        mx1 = fmaxf(mx1, __shfl_xor_sync(0xffffffffu, mx1, 1));
        mx1 = fmaxf(mx1, __shfl_xor_sync(0xffffffffu, mx1, 2));
        float mn0 = fmaxf(m0, mx0), mn1 = fmaxf(m1, mx1);
        float corr0 = __expf(m0 - mn0), corr1 = __expf(m1 - mn1);
        m0 = mn0; m1 = mn1;
        float sum0 = 0.f, sum1 = 0.f;
        #pragma unroll
        for (int j = 0; j < 8; j++) {
            sc[j][0] = __expf(sc[j][0] - mn0); sum0 += sc[j][0];
            sc[j][1] = __expf(sc[j][1] - mn0); sum0 += sc[j][1];
            sc[j][2] = __expf(sc[j][2] - mn1); sum1 += sc[j][2];
            sc[j][3] = __expf(sc[j][3] - mn1); sum1 += sc[j][3];
        }
        sum0 += __shfl_xor_sync(0xffffffffu, sum0, 1);
        sum0 += __shfl_xor_sync(0xffffffffu, sum0, 2);
        sum1 += __shfl_xor_sync(0xffffffffu, sum1, 1);
        sum1 += __shfl_xor_sync(0xffffffffu, sum1, 2);
        l0 = l0 * corr0 + sum0;
        l1 = l1 * corr1 + sum1;
        #pragma unroll
        for (int j = 0; j < 8; j++) {
            oc[j][0] *= corr0; oc[j][1] *= corr0;
            oc[j][2] *= corr1; oc[j][3] *= corr1;
        }

        // ---- store P as A-fragments into kp (per-warp 16x64 stripe) ----
        {
            float* pb = kp + w * 1024;
            #pragma unroll
            for (int j = 0; j < 8; j++) {
                #pragma unroll
                for (int e = 0; e < 2; e++) {
                    int kcol = t * 2 + e;                 // col within 8-tile
                    int base = j * 128 + (g * 4 + (kcol & 3)) * 4 + ((kcol >= 4) ? 2 : 0);
                    pb[base + 0] = __uint_as_float(ftf32(sc[j][e]));       // row g
                    pb[base + 1] = __uint_as_float(ftf32(sc[j][2 + e]));   // row g+8
                }
            }
        }
        __syncthreads();

        // ---- O += P V (hi + lo) ----
        const float* pb = kp + w * 1024;
        #pragma unroll
        for (int kk = 0; kk < 8; kk++) {
            uint4 pf = *(const uint4*)&pb[kk * 128 + lane * 4];
            #pragma unroll
            for (int j = 0; j < 8; j++) {
                uint2 bh = *(const uint2*)&vhi[(kk * 8 + j) * 64 + lane * 2];
                MMA_TF32(oc[j], pf, bh);
                uint2 bl = *(const uint2*)&vlo[(kk * 8 + j) * 64 + lane * 2];
                MMA_TF32(oc[j], pf, bl);
            }
        }
    }

    // ---- epilogue ----
    float inv0 = 1.f / l0, inv1 = 1.f / l1;
    #pragma unroll
    for (int j = 0; j < 8; j++) {
        int c0 = j * 8 + t * 2;
        if (r0 < T) {
            float2 rr = make_float2(oc[j][0] * inv0, oc[j][1] * inv0);
            *(float2*)(op + (size_t)r0 * DM + c0) = rr;
        }
        if (r1 < T) {
            float2 rr = make_float2(oc[j][2] * inv1, oc[j][3] * inv1);
            *(float2*)(op + (size_t)r1 * DM + c0) = rr;
        }
    }
}

// ---------------- encoder ----------------
__global__ void enc_kernel(const float* __restrict__ x,
                           const float* __restrict__ W_enc,
                           const float* __restrict__ b_enc,
                           const float* __restrict__ cls_tok,
                           const float* __restrict__ pos_emb,
                           float* __restrict__ h)
{
    int row = blockIdx.x;
    int b = row / T, t = row % T;
    int tid = threadIdx.x;           // 128
    float* hr = h + (size_t)row * DM;
    if (t == 0) {
        for (int d = tid; d < DM; d += 128)
            hr[d] = cls_tok[d] + pos_emb[d];
        return;
    }
    __shared__ float xs[NTOK];
    if (tid < NTOK) xs[tid] = x[(size_t)b * SEQ * NTOK + (size_t)(t - 1) * NTOK + tid];
    __syncthreads();
    for (int d = tid; d < DM; d += 128) {
        float acc = b_enc[d] + pos_emb[(size_t)t * DM + d];
        #pragma unroll 17
        for (int kk = 0; kk < NTOK; kk++)
            acc += xs[kk] * W_enc[kk * DM + d];
        hr[d] = acc;
    }
}

// ---------------- residual add + layernorm ----------------
__global__ void add_ln_kernel(float* __restrict__ h, const float* __restrict__ f,
                              const float* __restrict__ gamma, const float* __restrict__ beta)
{
    int row = blockIdx.x;
    int tid = threadIdx.x;  // 128
    float* hr = h + (size_t)row * DM;
    const float* fr = f + (size_t)row * DM;
    float v[4];
    float s = 0.f;
    #pragma unroll
    for (int i = 0; i < 4; i++) {
        v[i] = hr[tid + 128 * i] + fr[tid + 128 * i];
        s += v[i];
    }
    __shared__ float sm2[4];
    int lane = tid & 31, warp = tid >> 5;
    #pragma unroll
    for (int off = 16; off >= 1; off >>= 1) s += __shfl_xor_sync(0xffffffffu, s, off);
    if (lane == 0) sm2[warp] = s;
    __syncthreads();
    float mean = (sm2[0] + sm2[1] + sm2[2] + sm2[3]) * (1.f / DM);
    float vs = 0.f;
    #pragma unroll
    for (int i = 0; i < 4; i++) { float d = v[i] - mean; vs += d * d; }
    __syncthreads();
    #pragma unroll
    for (int off = 16; off >= 1; off >>= 1) vs += __shfl_xor_sync(0xffffffffu, vs, off);
    if (lane == 0) sm2[warp] = vs;
    __syncthreads();
    float var = (sm2[0] + sm2[1] + sm2[2] + sm2[3]) * (1.f / DM);
    float inv = rsqrtf(var + 1e-5f);
    #pragma unroll
    for (int i = 0; i < 4; i++) {
        int d = tid + 128 * i;
        hr[d] = (v[i] - mean) * inv * gamma[d] + beta[d];
    }
}

// ---------------- classification head ----------------
__global__ void head_kernel(const float* __restrict__ h,
                            const float* __restrict__ Wd1, const float* __restrict__ bd1,
                            const float* __restrict__ Wd2, const float* __restrict__ bd2,
                            float* __restrict__ out)
{
    __shared__ float mid[NB][MLPD];
    int tid = threadIdx.x; // 256
    for (int b = 0; b < NB; b++) {
        const float* cls = h + (size_t)b * T * DM;
        float acc = bd1[tid];
        for (int kk = 0; kk < DM; kk++)
            acc += cls[kk] * Wd1[kk * MLPD + tid];
        mid[b][tid] = acc;
    }
    __syncthreads();
    if (tid < NB * CLASSES) {
        int b = tid / CLASSES, c = tid % CLASSES;
        float acc = bd2[c];
        for (int m = 0; m < MLPD; m++)
            acc += mid[b][m] * Wd2[m * CLASSES + c];
        out[b * CLASSES + c] = acc;
    }
}

// ---------------- GAT branch: one warp per graph, no smem/barriers ----------------
__global__ __launch_bounds__(256) void gat_kernel(
    const float* __restrict__ x, const int* __restrict__ adj,
    const float* __restrict__ Wg, const float* __restrict__ ag,
    const float* __restrict__ Wgo, const float* __restrict__ ago,
    float* __restrict__ out)
{
    int wid = threadIdx.x >> 5, lane = threadIdx.x & 31;
    int gidx = blockIdx.x * 8 + wid;    // grid 640 * 8 warps = 5120 exact
    int s = gidx / 5, g = gidx % 5;

    // node features (broadcast loads; same address across warp)
    float xg[5][3];
    const float* xb = x + (size_t)s * NTOK + g * 3;
    #pragma unroll
    for (int n = 0; n < 5; n++)
        #pragma unroll
        for (int c = 0; c < 3; c++)
            xg[n][c] = xb[(size_t)n * SEQ * NTOK + c];

    // adjacency as 25-bit mask in every lane
    int av = (lane < 25) ? adj[lane] : 0;
    unsigned mb = __ballot_sync(0xffffffffu, av > 0);

    float hcat[GH][5][2];   // lane owns features f=lane, f=lane+32
    #pragma unroll
    for (int hd = 0; hd < GH; hd++) {
        const float* W = Wg + hd * 3 * GHID;
        float w00 = W[lane],      w01 = W[GHID + lane],      w02 = W[2 * GHID + lane];
        float w10 = W[32 + lane], w11 = W[GHID + 32 + lane], w12 = W[2 * GHID + 32 + lane];
        float a1l = ag[hd * 2 * GHID + lane];
        float a1h = ag[hd * 2 * GHID + 32 + lane];
        float a2l = ag[hd * 2 * GHID + GHID + lane];
        float a2h = ag[hd * 2 * GHID + GHID + 32 + lane];
        float hv[5][2];
        #pragma unroll
        for (int n = 0; n < 5; n++) {
            hv[n][0] = xg[n][0] * w00 + xg[n][1] * w01 + xg[n][2] * w02;
            hv[n][1] = xg[n][0] * w10 + xg[n][1] * w11 + xg[n][2] * w12;
        }
        float s1[5], s2[5];
        #pragma unroll
        for (int n = 0; n < 5; n++) {
            float p1 = hv[n][0] * a1l + hv[n][1] * a1h;
            float p2 = hv[n][0] * a2l + hv[n][1] * a2h;
            #pragma unroll
            for (int off = 16; off >= 1; off >>= 1) {
                p1 += __shfl_xor_sync(0xffffffffu, p1, off);
                p2 += __shfl_xor_sync(0xffffffffu, p2, off);
            }
            s1[n] = p1; s2[n] = p2;
        }
        float att[5][5];
        #pragma unroll
        for (int i = 0; i < 5; i++) {
            float ev[5], mx = -1e30f;
            #pragma unroll
            for (int j = 0; j < 5; j++) {
                if ((mb >> (i * 5 + j)) & 1) {
                    float e = s1[i] + s2[j];
                    e = e > 0.f ? e : 0.2f * e;
                    ev[j] = e;
                    mx = fmaxf(mx, e);
                } else ev[j] = -1e30f;
            }
            float sum = 0.f;
            #pragma unroll
            for (int j = 0; j < 5; j++) {
                float p = ((mb >> (i * 5 + j)) & 1) ? __expf(ev[j] - mx) : 0.f;
                att[i][j] = p; sum += p;
            }
            float inv = 1.f / sum;
            #pragma unroll
            for (int j = 0; j < 5; j++) att[i][j] *= inv;
        }
        #pragma unroll
        for (int n = 0; n < 5; n++) {
            float o0 = 0.f, o1 = 0.f;
            #pragma unroll
            for (int j = 0; j < 5; j++) {
                o0 += att[n][j] * hv[j][0];
                o1 += att[n][j] * hv[j][1];
            }
            hcat[hd][n][0] = o0 > 0.f ? o0 : expm1f(o0);
            hcat[hd][n][1] = o1 > 0.f ? o1 : expm1f(o1);
        }
    }

    // output layer: h2[n][m] = sum_k hcat[n][k] * Wgo[k][m] (k distributed over lanes)
    float wg0[GH][GCLS], wg1[GH][GCLS];
    #pragma unroll
    for (int hd = 0; hd < GH; hd++)
        #pragma unroll
        for (int m = 0; m < GCLS; m++) {
            wg0[hd][m] = Wgo[(hd * GHID + lane) * GCLS + m];
            wg1[hd][m] = Wgo[(hd * GHID + 32 + lane) * GCLS + m];
        }
    float h2[5][5];
    #pragma unroll
    for (int n = 0; n < 5; n++)
        #pragma unroll
        for (int m = 0; m < 5; m++) {
            float acc = 0.f;
            #pragma unroll
            for (int hd = 0; hd < GH; hd++)
                acc += hcat[hd][n][0] * wg0[hd][m] + hcat[hd][n][1] * wg1[hd][m];
            #pragma unroll
            for (int off = 16; off >= 1; off >>= 1)
                acc += __shfl_xor_sync(0xffffffffu, acc, off);
            h2[n][m] = acc;
        }

    // output GAT attention (computed redundantly in every lane; h2 identical across lanes)
    float s1o[5], s2o[5];
    #pragma unroll
    for (int n = 0; n < 5; n++) {
        float a1 = 0.f, a2 = 0.f;
        #pragma unroll
        for (int m = 0; m < 5; m++) {
            a1 += h2[n][m] * ago[m];
            a2 += h2[n][m] * ago[GCLS + m];
        }
        s1o[n] = a1; s2o[n] = a2;
    }
    float att2[5][5];
    #pragma unroll
    for (int i = 0; i < 5; i++) {
        float ev[5], mx = -1e30f;
        #pragma unroll
        for (int j = 0; j < 5; j++) {
            if ((mb >> (i * 5 + j)) & 1) {
                float e = s1o[i] + s2o[j];
                e = e > 0.f ? e : 0.2f * e;
                ev[j] = e;
                mx = fmaxf(mx, e);
            } else ev[j] = -1e30f;
        }
        float sum = 0.f;
        #pragma unroll
        for (int j = 0; j < 5; j++) {
            float p = ((mb >> (i * 5 + j)) & 1) ? __expf(ev[j] - mx) : 0.f;
            att2[i][j] = p; sum += p;
        }
        float inv = 1.f / sum;
        #pragma unroll
        for (int j = 0; j < 5; j++) att2[i][j] *= inv;
    }
    float o2[5][5];
    #pragma unroll
    for (int n = 0; n < 5; n++)
        #pragma unroll
        for (int m = 0; m < 5; m++) {
            float o = 0.f;
            #pragma unroll
            for (int j = 0; j < 5; j++) o += att2[n][j] * h2[j][m];
            o2[n][m] = o > 0.f ? o : expm1f(o);
        }
    if (lane < 25) {
        int n = lane / 5;
        float mx = -1e30f;
        #pragma unroll
        for (int m = 0; m < 5; m++) mx = fmaxf(mx, o2[n][m]);
        float sum = 0.f;
        #pragma unroll
        for (int m = 0; m < 5; m++) sum += __expf(o2[n][m] - mx);
        float lse = mx + logf(sum);
        out[OUT_GAT_BASE + (size_t)gidx * 25 + lane] = o2[n][lane % 5] - lse;
    }
}

// ---------------- host orchestration ----------------
extern "C" void kernel_launch(void* const* d_in, const int* in_sizes, int n_in,
                              void* d_out, int out_size)
{
    const float* x       = (const float*)d_in[0];
    const int*   adj     = (const int*)  d_in[1];
    const float* W_enc   = (const float*)d_in[2];
    const float* b_enc   = (const float*)d_in[3];
    const float* cls_tok = (const float*)d_in[4];
    const float* pos_emb = (const float*)d_in[5];
    const float* Wq      = (const float*)d_in[6];
    const float* bq      = (const float*)d_in[7];
    const float* Wk      = (const float*)d_in[8];
    const float* bk      = (const float*)d_in[9];
    const float* Wv      = (const float*)d_in[10];
    const float* bv      = (const float*)d_in[11];
    const float* Wo      = (const float*)d_in[12];
    const float* bo      = (const float*)d_in[13];
    const float* W1      = (const float*)d_in[14];
    const float* b1      = (const float*)d_in[15];
    const float* W2      = (const float*)d_in[16];
    const float* b2      = (const float*)d_in[17];
    const float* g1      = (const float*)d_in[18];
    const float* be1     = (const float*)d_in[19];
    const float* g2      = (const float*)d_in[20];
    const float* be2     = (const float*)d_in[21];
    const float* Wd1     = (const float*)d_in[22];
    const float* bd1     = (const float*)d_in[23];
    const float* Wd2     = (const float*)d_in[24];
    const float* bd2     = (const float*)d_in[25];
    const float* Wg      = (const float*)d_in[26];
    const float* ag      = (const float*)d_in[27];
    const float* Wgo     = (const float*)d_in[28];
    const float* ago     = (const float*)d_in[29];
    float* out = (float*)d_out;

    float *h, *q, *k, *v, *ao, *t, *ff;
    float *WqT, *WkT, *WvT, *WoT, *W1T, *W2T;
    cudaGetSymbolAddress((void**)&h,   g_h);
    cudaGetSymbolAddress((void**)&q,   g_q);
    cudaGetSymbolAddress((void**)&k,   g_k);
    cudaGetSymbolAddress((void**)&v,   g_v);
    cudaGetSymbolAddress((void**)&ao,  g_ao);
    cudaGetSymbolAddress((void**)&t,   g_t);
    cudaGetSymbolAddress((void**)&ff,  g_ff);
    cudaGetSymbolAddress((void**)&WqT, g_WqT);
    cudaGetSymbolAddress((void**)&WkT, g_WkT);
    cudaGetSymbolAddress((void**)&WvT, g_WvT);
    cudaGetSymbolAddress((void**)&WoT, g_WoT);
    cudaGetSymbolAddress((void**)&W1T, g_W1T);
    cudaGetSymbolAddress((void**)&W2T, g_W2T);

    cudaFuncSetAttribute(mma_gemm, cudaFuncAttributeMaxDynamicSharedMemorySize, MM_SMEM);
    cudaFuncSetAttribute(mma_gemm_qkv, cudaFuncAttributeMaxDynamicSharedMemorySize, MM_SMEM);
    cudaFuncSetAttribute(attn_mma_kernel, cudaFuncAttributeMaxDynamicSharedMemorySize, ATT_SMEM);

    // all weight transposes (tf32-rounded) in one launch
    transpose_all<<<12288, 256>>>(Wq, Wk, Wv, Wo, W1, W2, WqT, WkT, WvT, WoT, W1T, W2T);

    gat_kernel<<<GAT_GRAPHS / 8, 256>>>(x, adj, Wg, ag, Wgo, ago, out);
    enc_kernel<<<MROWS, 128>>>(x, W_enc, b_enc, cls_tok, pos_emb, h);

    int gy = (MROWS + 127) / 128;    // 41
    dim3 grid_qkv(DM / 128, gy, 3);
    dim3 grid_dm(DM / 128, gy);
    dim3 grid_ff(DFF / 128, gy);
    dim3 attn_grid((T + 127) / 128, NHEAD, NB);   // 9 x 8 x 5

    for (int l = 0; l < NL; l++) {
        mma_gemm_qkv<<<grid_qkv, 256, MM_SMEM>>>(
            h, WqT + (size_t)l * DM * DM, WkT + (size_t)l * DM * DM, WvT + (size_t)l * DM * DM,
            bq + l * DM, bk + l * DM, bv + l * DM, q, k, v);
        attn_mma_kernel<<<attn_grid, 256, ATT_SMEM>>>(q, k, v, ao);
        mma_gemm<<<grid_dm, 256, MM_SMEM>>>(ao, WoT + (size_t)l * DM * DM, bo + l * DM, t, MROWS, DM, DM, 0);
        add_ln_kernel<<<MROWS, 128>>>(h, t, g1 + l * DM, be1 + l * DM);
        mma_gemm<<<grid_ff, 256, MM_SMEM>>>(h, W1T + (size_t)l * DM * DFF, b1 + l * DFF, ff, MROWS, DFF, DM, 1);
        mma_gemm<<<grid_dm, 256, MM_SMEM>>>(ff, W2T + (size_t)l * DFF * DM, b2 + l * DM, t, MROWS, DM, DFF, 0);
        add_ln_kernel<<<MROWS, 128>>>(h, t, g2 + l * DM, be2 + l * DM);
    }

    head_kernel<<<1, 256>>>(h, Wd1, bd1, Wd2, bd2, out);
}

// round 7
// speedup vs baseline: 2.1658x; 1.0698x over previous
#include <cuda_runtime.h>
#include <cuda_bf16.h>
#include <math.h>
#include <stdint.h>

// ---------------- problem constants ----------------
#define NB 5
#define SEQ 1024
#define T 1025
#define DM 512
#define NHEAD 8
#define HD 64
#define DFF 2048
#define NL 4
#define NTOK 51
#define MLPD 256
#define CLASSES 7
#define GH 3
#define GHID 64
#define GCLS 5
#define MROWS (NB * T)
#define GAT_GRAPHS (SEQ * 5)
#define OUT_GAT_BASE (NB * CLASSES)

// ---------------- scratch ----------------
__device__ float g_h [MROWS * DM];
__device__ float g_q [MROWS * DM];
__device__ float g_k [MROWS * DM];
__device__ float g_v [MROWS * DM];
__device__ float g_ao[MROWS * DM];
__device__ float g_t [MROWS * DM];
__device__ float g_ff[MROWS * DFF];
// fragment-packed (tf32-rounded) weights: [ntile][ktile][lane][2] words
__device__ float g_WqF[NL * DM * DM];
__device__ float g_WkF[NL * DM * DM];
__device__ float g_WvF[NL * DM * DM];
__device__ float g_WoF[NL * DM * DM];
__device__ float g_W1F[NL * DM * DFF];
__device__ float g_W2F[NL * DFF * DM];

// ---------------- helpers ----------------
__device__ __forceinline__ uint32_t ftf32(float x) {
    uint32_t r;
    asm("cvt.rna.tf32.f32 %0, %1;" : "=r"(r) : "f"(x));
    return r;
}

#define MMA_TF32(d, a, b) \
    asm volatile("mma.sync.aligned.m16n8k8.row.col.f32.tf32.tf32.f32 " \
        "{%0,%1,%2,%3}, {%4,%5,%6,%7}, {%8,%9}, {%0,%1,%2,%3};" \
        : "+f"((d)[0]), "+f"((d)[1]), "+f"((d)[2]), "+f"((d)[3]) \
        : "r"((a).x), "r"((a).y), "r"((a).z), "r"((a).w), \
          "r"((b).x), "r"((b).y))

#define MMA_TF32_P(d, a0, a1, a2, a3, b) \
    asm volatile("mma.sync.aligned.m16n8k8.row.col.f32.tf32.tf32.f32 " \
        "{%0,%1,%2,%3}, {%4,%5,%6,%7}, {%8,%9}, {%0,%1,%2,%3};" \
        : "+f"((d)[0]), "+f"((d)[1]), "+f"((d)[2]), "+f"((d)[3]) \
        : "r"(a0), "r"(a1), "r"(a2), "r"(a3), \
          "r"((b).x), "r"((b).y))

// ---------------- weight -> B-fragment packing (one launch) ----------------
// out[((ntile*(K/8) + ktile)*64) + lane*2 + r] = tf32(W[ktile*8 + (lane&3) + r*4][ntile*8 + (lane>>2)])
// jobs: 0..3 = Wq,Wk,Wv,Wo (512x512, 1024 blocks each); 4 = W1; 5 = W2 (4096 blocks each)
__global__ __launch_bounds__(256) void frag_all(
    const float* __restrict__ Wq, const float* __restrict__ Wk,
    const float* __restrict__ Wv, const float* __restrict__ Wo,
    const float* __restrict__ W1, const float* __restrict__ W2,
    float* __restrict__ WqF, float* __restrict__ WkF,
    float* __restrict__ WvF, float* __restrict__ WoF,
    float* __restrict__ W1F, float* __restrict__ W2F)
{
    __shared__ float t[32][33];   // [k_local][n_local]
    int bid = blockIdx.x;
    const float* W; float* Wf; int K, N, rel, nx;
    if (bid < 4096) {
        int job = bid >> 10; rel = bid & 1023;
        K = DM; N = DM; nx = 16;
        if (job == 0)      { W = Wq; Wf = WqF; }
        else if (job == 1) { W = Wk; Wf = WkF; }
        else if (job == 2) { W = Wv; Wf = WvF; }
        else               { W = Wo; Wf = WoF; }
    } else if (bid < 8192) {
        rel = bid - 4096; K = DM; N = DFF; nx = 64;
        W = W1; Wf = W1F;
    } else {
        rel = bid - 8192; K = DFF; N = DM; nx = 16;
        W = W2; Wf = W2F;
    }
    int ny = K >> 5;
    int per = nx * ny;
    int l = rel / per, r2 = rel % per;
    int n0 = (r2 % nx) * 32, k0 = (r2 / nx) * 32;
    const float* w = W + (size_t)l * K * N;
    float* o = Wf + (size_t)l * K * N;
    int tx = threadIdx.x & 31, ty = threadIdx.x >> 5;
    #pragma unroll
    for (int i = 0; i < 32; i += 8)
        t[ty + i][tx] = w[(size_t)(k0 + ty + i) * N + n0 + tx];
    __syncthreads();
    int Kt = K >> 3;
    #pragma unroll
    for (int it = 0; it < 4; it++) {
        int w2 = threadIdx.x + it * 256;
        int group = w2 >> 6, within = w2 & 63;
        int ktl = group & 3, ntl = group >> 2;
        int lane = within >> 1, r = within & 1;
        int kk = ktl * 8 + (lane & 3) + r * 4;
        int nn = ntl * 8 + (lane >> 2);
        o[((size_t)((n0 >> 3) + ntl) * Kt + (k0 >> 3) + ktl) * 64 + within]
            = __uint_as_float(ftf32(t[kk][nn]));
    }
}

// ---------------- tf32 mma.sync GEMM: C = A @ W^T + bias ----------------
// B-fragments loaded directly from global (L2-resident), A staged in SMEM.
// 128x128x32 CTA tile, 8 warps, 64x32 warp tile, ping-pong A SMEM (32KB).
#define MM_SMEM 32768

__device__ __forceinline__ void mma_gemm_body(
    const float* __restrict__ A, const float* __restrict__ Bf,
    const float* __restrict__ bias, float* __restrict__ C,
    int M, int N, int K, int relu)
{
    extern __shared__ float sm[];
    int tid = threadIdx.x;
    int w = tid >> 5, lane = tid & 31;
    int bm = blockIdx.y * 128, bn = blockIdx.x * 128;
    int wm = (w & 1) * 64;
    int wn = (w >> 1) * 32;
    int Kt = K >> 3;
    int nt0 = (bn + wn) >> 3;

    float d[4][4][4];
    #pragma unroll
    for (int i = 0; i < 4; i++)
        #pragma unroll
        for (int j = 0; j < 4; j++)
            #pragma unroll
            for (int e = 0; e < 4; e++) d[i][j][e] = 0.f;

    uint4 ra[4];
    int nch = K >> 5;

    // ---- prologue: A chunk 0 ----
    #pragma unroll
    for (int it = 0; it < 4; it++) {
        int idx = tid + it * 256;
        int r = idx >> 3, c4 = (idx & 7) << 2;
        float4 av = make_float4(0.f, 0.f, 0.f, 0.f);
        if (bm + r < M) av = *(const float4*)(A + (size_t)(bm + r) * K + c4);
        ra[it].x = ftf32(av.x); ra[it].y = ftf32(av.y);
        ra[it].z = ftf32(av.z); ra[it].w = ftf32(av.w);
    }
    {
        uint32_t* As = (uint32_t*)sm;
        #pragma unroll
        for (int it = 0; it < 4; it++) {
            int idx = tid + it * 256;
            int r = idx >> 3, c4 = (idx & 7) << 2;
            int kt = c4 >> 3, kin0 = c4 & 7;
            int mt = r >> 4, rin = r & 15;
            int regA = (kin0 ? 2 : 0) + ((rin >> 3) & 1);
            uint32_t* dA = As + ((kt * 8 + mt) * 32 + (rin & 7) * 4) * 4 + regA;
            dA[0] = ra[it].x; dA[4] = ra[it].y; dA[8] = ra[it].z; dA[12] = ra[it].w;
        }
    }
    // first B-frags (ktg = 0)
    uint2 bc[4], bnx[4];
    #pragma unroll
    for (int j = 0; j < 4; j++)
        bc[j] = *(const uint2*)(Bf + ((size_t)(nt0 + j) * Kt) * 64 + lane * 2);
    __syncthreads();

    for (int c = 0; c < nch; c++) {
        int buf = c & 1;
        uint32_t* As = (uint32_t*)sm + buf * 4096;

        // prefetch next A chunk into registers
        if (c + 1 < nch) {
            int k0 = (c + 1) << 5;
            #pragma unroll
            for (int it = 0; it < 4; it++) {
                int idx = tid + it * 256;
                int r = idx >> 3, c4 = (idx & 7) << 2;
                float4 av = make_float4(0.f, 0.f, 0.f, 0.f);
                if (bm + r < M) av = *(const float4*)(A + (size_t)(bm + r) * K + k0 + c4);
                ra[it].x = ftf32(av.x); ra[it].y = ftf32(av.y);
                ra[it].z = ftf32(av.z); ra[it].w = ftf32(av.w);
            }
        }

        #pragma unroll
        for (int kt = 0; kt < 4; kt++) {
            int ktg = (c << 2) + kt;
            // prefetch next kt's B-frags from global (L2)
            if (ktg + 1 < Kt) {
                #pragma unroll
                for (int j = 0; j < 4; j++)
                    bnx[j] = *(const uint2*)(Bf + ((size_t)(nt0 + j) * Kt + ktg + 1) * 64 + lane * 2);
            }
            uint4 af[4];
            #pragma unroll
            for (int i = 0; i < 4; i++)
                af[i] = *(uint4*)(As + ((kt * 8 + (wm >> 4) + i) * 32 + lane) * 4);
            #pragma unroll
            for (int i = 0; i < 4; i++)
                #pragma unroll
                for (int j = 0; j < 4; j++)
                    MMA_TF32(d[i][j], af[i], bc[j]);
            #pragma unroll
            for (int j = 0; j < 4; j++) bc[j] = bnx[j];
        }
        __syncthreads();

        if (c + 1 < nch) {
            uint32_t* As2 = (uint32_t*)sm + (buf ^ 1) * 4096;
            #pragma unroll
            for (int it = 0; it < 4; it++) {
                int idx = tid + it * 256;
                int r = idx >> 3, c4 = (idx & 7) << 2;
                int kt = c4 >> 3, kin0 = c4 & 7;
                int mt = r >> 4, rin = r & 15;
                int regA = (kin0 ? 2 : 0) + ((rin >> 3) & 1);
                uint32_t* dA = As2 + ((kt * 8 + mt) * 32 + (rin & 7) * 4) * 4 + regA;
                dA[0] = ra[it].x; dA[4] = ra[it].y; dA[8] = ra[it].z; dA[12] = ra[it].w;
            }
            __syncthreads();
        }
    }

    int g = lane >> 2, t2 = (lane & 3) << 1;
    #pragma unroll
    for (int i = 0; i < 4; i++) {
        #pragma unroll
        for (int hh = 0; hh < 2; hh++) {
            int row = bm + wm + i * 16 + g + hh * 8;
            if (row >= M) continue;
            #pragma unroll
            for (int j = 0; j < 4; j++) {
                int col = bn + wn + j * 8 + t2;
                float2 bb = *(const float2*)(bias + col);
                float2 r;
                r.x = d[i][j][hh * 2 + 0] + bb.x;
                r.y = d[i][j][hh * 2 + 1] + bb.y;
                if (relu) { r.x = fmaxf(r.x, 0.f); r.y = fmaxf(r.y, 0.f); }
                *(float2*)(C + (size_t)row * N + col) = r;
            }
        }
    }
}

__global__ __launch_bounds__(256) void mma_gemm(
    const float* __restrict__ A, const float* __restrict__ Bf,
    const float* __restrict__ bias, float* __restrict__ C,
    int M, int N, int K, int relu)
{
    mma_gemm_body(A, Bf, bias, C, M, N, K, relu);
}

__global__ __launch_bounds__(256) void mma_gemm_qkv(
    const float* __restrict__ A,
    const float* __restrict__ WqF, const float* __restrict__ WkF, const float* __restrict__ WvF,
    const float* __restrict__ bq, const float* __restrict__ bk, const float* __restrict__ bv,
    float* __restrict__ q, float* __restrict__ k, float* __restrict__ v)
{
    const float* Bf; const float* bias; float* C;
    if (blockIdx.z == 0)      { Bf = WqF; bias = bq; C = q; }
    else if (blockIdx.z == 1) { Bf = WkF; bias = bk; C = k; }
    else                      { Bf = WvF; bias = bv; C = v; }
    mma_gemm_body(A, Bf, bias, C, MROWS, DM, DM, 0);
}

// ---------------- tf32 mma.sync flash attention, 128-row q-tile ----------------
#define ATT_SMEM 65536

__global__ __launch_bounds__(256) void attn_mma_kernel(
    const float* __restrict__ q, const float* __restrict__ k,
    const float* __restrict__ v, float* __restrict__ o)
{
    extern __shared__ float as_[];
    float* kp  = as_;            // K B-frags (4096) then P A-frags (8192 total)
    float* vhi = as_ + 8192;
    float* vlo = as_ + 12288;

    int tid = threadIdx.x;
    int w = tid >> 5, lane = tid & 31;
    int g = lane >> 2, t = lane & 3;
    int qb = blockIdx.x * 128;
    int head = blockIdx.y, b = blockIdx.z;
    const size_t bs = (size_t)T * DM;
    const float* qp = q + b * bs + head * HD;
    const float* kpg = k + b * bs + head * HD;
    const float* vpg = v + b * bs + head * HD;
    float* op = o + b * bs + head * HD;

    int r0 = qb + w * 16 + g;
    int r1 = r0 + 8;
    uint32_t aq[8][4];
    #pragma unroll
    for (int kk = 0; kk < 8; kk++) {
        int d0 = kk * 8 + t, d1 = d0 + 4;
        float q00 = 0.f, q01 = 0.f, q10 = 0.f, q11 = 0.f;
        if (r0 < T) { q00 = qp[(size_t)r0 * DM + d0]; q01 = qp[(size_t)r0 * DM + d1]; }
        if (r1 < T) { q10 = qp[(size_t)r1 * DM + d0]; q11 = qp[(size_t)r1 * DM + d1]; }
        aq[kk][0] = ftf32(q00 * 0.125f);
        aq[kk][1] = ftf32(q10 * 0.125f);
        aq[kk][2] = ftf32(q01 * 0.125f);
        aq[kk][3] = ftf32(q11 * 0.125f);
    }

    float oc[8][4];
    #pragma unroll
    for (int j = 0; j < 8; j++)
        #pragma unroll
        for (int e = 0; e < 4; e++) oc[j][e] = 0.f;
    float m0 = -1e30f, m1 = -1e30f, l0 = 0.f, l1 = 0.f;

    for (int kb = 0; kb < T; kb += 64) {
        __syncthreads();
        for (int idx = tid; idx < 4096; idx += 256) {
            int key = idx >> 6, dd = idx & 63;
            int s = kb + key;
            float kv = 0.f, vv = 0.f;
            if (s < T) {
                kv = kpg[(size_t)s * DM + dd];
                vv = vpg[(size_t)s * DM + dd];
            }
            kp[((dd >> 3) * 8 + (key >> 3)) * 64 + ((key & 7) * 4 + (dd & 3)) * 2 + ((dd & 7) >> 2)]
                = __uint_as_float(ftf32(kv));
            uint32_t hb = ftf32(vv);
            float hf = __uint_as_float(hb);
            uint32_t lb = ftf32(vv - hf);
            int a2 = ((key >> 3) * 8 + (dd >> 3)) * 64 + ((dd & 7) * 4 + (key & 3)) * 2 + ((key & 7) >> 2);
            vhi[a2] = __uint_as_float(hb);
            vlo[a2] = __uint_as_float(lb);
        }
        __syncthreads();

        float sc[8][4];
        #pragma unroll
        for (int j = 0; j < 8; j++)
            #pragma unroll
            for (int e = 0; e < 4; e++) sc[j][e] = 0.f;
        #pragma unroll
        for (int kk = 0; kk < 8; kk++) {
            #pragma unroll
            for (int j = 0; j < 8; j++) {
                uint2 bf = *(const uint2*)&kp[(kk * 8 + j) * 64 + lane * 2];
                MMA_TF32_P(sc[j], aq[kk][0], aq[kk][1], aq[kk][2], aq[kk][3], bf);
            }
        }
        __syncthreads();

        int rem = T - kb;
        if (rem < 64) {
            #pragma unroll
            for (int j = 0; j < 8; j++) {
                int c0 = j * 8 + t * 2, c1 = c0 + 1;
                if (c0 >= rem) { sc[j][0] = -1e30f; sc[j][2] = -1e30f; }
                if (c1 >= rem) { sc[j][1] = -1e30f; sc[j][3] = -1e30f; }
            }
        }
        float mx0 = -1e30f, mx1 = -1e30f;
        #pragma unroll
        for (int j = 0; j < 8; j++) {
            mx0 = fmaxf(mx0, fmaxf(sc[j][0], sc[j][1]));
            mx1 = fmaxf(mx1, fmaxf(sc[j][2], sc[j][3]));
        }
        mx0 = fmaxf(mx0, __shfl_xor_sync(0xffffffffu, mx0, 1));
        mx0 = fmaxf(mx0, __shfl_xor_sync(0xffffffffu, mx0, 2));
        mx1 = fmaxf(mx1, __shfl_xor_sync(0xffffffffu, mx1, 1));
        mx1 = fmaxf(mx1, __shfl_xor_sync(0xffffffffu, mx1, 2));
        float mn0 = fmaxf(m0, mx0), mn1 = fmaxf(m1, mx1);
        float corr0 = __expf(m0 - mn0), corr1 = __expf(m1 - mn1);
        m0 = mn0; m1 = mn1;
        float sum0 = 0.f, sum1 = 0.f;
        #pragma unroll
        for (int j = 0; j < 8; j++) {
            sc[j][0] = __expf(sc[j][0] - mn0); sum0 += sc[j][0];
            sc[j][1] = __expf(sc[j][1] - mn0); sum0 += sc[j][1];
            sc[j][2] = __expf(sc[j][2] - mn1); sum1 += sc[j][2];
            sc[j][3] = __expf(sc[j][3] - mn1); sum1 += sc[j][3];
        }
        sum0 += __shfl_xor_sync(0xffffffffu, sum0, 1);
        sum0 += __shfl_xor_sync(0xffffffffu, sum0, 2);
        sum1 += __shfl_xor_sync(0xffffffffu, sum1, 1);
        sum1 += __shfl_xor_sync(0xffffffffu, sum1, 2);
        l0 = l0 * corr0 + sum0;
        l1 = l1 * corr1 + sum1;
        #pragma unroll
        for (int j = 0; j < 8; j++) {
            oc[j][0] *= corr0; oc[j][1] *= corr0;
            oc[j][2] *= corr1; oc[j][3] *= corr1;
        }

        {
            float* pb = kp + w * 1024;
            #pragma unroll
            for (int j = 0; j < 8; j++) {
                #pragma unroll
                for (int e = 0; e < 2; e++) {
                    int kcol = t * 2 + e;
                    int base = j * 128 + (g * 4 + (kcol & 3)) * 4 + ((kcol >= 4) ? 2 : 0);
                    pb[base + 0] = __uint_as_float(ftf32(sc[j][e]));
                    pb[base + 1] = __uint_as_float(ftf32(sc[j][2 + e]));
                }
            }
        }
        __syncthreads();

        const float* pb = kp + w * 1024;
        #pragma unroll
        for (int kk = 0; kk < 8; kk++) {
            uint4 pf = *(const uint4*)&pb[kk * 128 + lane * 4];
            #pragma unroll
            for (int j = 0; j < 8; j++) {
                uint2 bh = *(const uint2*)&vhi[(kk * 8 + j) * 64 + lane * 2];
                MMA_TF32(oc[j], pf, bh);
                uint2 bl = *(const uint2*)&vlo[(kk * 8 + j) * 64 + lane * 2];
                MMA_TF32(oc[j], pf, bl);
            }
        }
    }

    float inv0 = 1.f / l0, inv1 = 1.f / l1;
    #pragma unroll
    for (int j = 0; j < 8; j++) {
        int c0 = j * 8 + t * 2;
        if (r0 < T) {
            float2 rr = make_float2(oc[j][0] * inv0, oc[j][1] * inv0);
            *(float2*)(op + (size_t)r0 * DM + c0) = rr;
        }
        if (r1 < T) {
            float2 rr = make_float2(oc[j][2] * inv1, oc[j][3] * inv1);
            *(float2*)(op + (size_t)r1 * DM + c0) = rr;
        }
    }
}

// ---------------- encoder ----------------
__global__ void enc_kernel(const float* __restrict__ x,
                           const float* __restrict__ W_enc,
                           const float* __restrict__ b_enc,
                           const float* __restrict__ cls_tok,
                           const float* __restrict__ pos_emb,
                           float* __restrict__ h)
{
    int row = blockIdx.x;
    int b = row / T, t = row % T;
    int tid = threadIdx.x;           // 128
    float* hr = h + (size_t)row * DM;
    if (t == 0) {
        for (int d = tid; d < DM; d += 128)
            hr[d] = cls_tok[d] + pos_emb[d];
        return;
    }
    __shared__ float xs[NTOK];
    if (tid < NTOK) xs[tid] = x[(size_t)b * SEQ * NTOK + (size_t)(t - 1) * NTOK + tid];
    __syncthreads();
    for (int d = tid; d < DM; d += 128) {
        float acc = b_enc[d] + pos_emb[(size_t)t * DM + d];
        #pragma unroll 17
        for (int kk = 0; kk < NTOK; kk++)
            acc += xs[kk] * W_enc[kk * DM + d];
        hr[d] = acc;
    }
}

// ---------------- residual add + layernorm ----------------
__global__ void add_ln_kernel(float* __restrict__ h, const float* __restrict__ f,
                              const float* __restrict__ gamma, const float* __restrict__ beta)
{
    int row = blockIdx.x;
    int tid = threadIdx.x;  // 128
    float* hr = h + (size_t)row * DM;
    const float* fr = f + (size_t)row * DM;
    float v[4];
    float s = 0.f;
    #pragma unroll
    for (int i = 0; i < 4; i++) {
        v[i] = hr[tid + 128 * i] + fr[tid + 128 * i];
        s += v[i];
    }
    __shared__ float sm2[4];
    int lane = tid & 31, warp = tid >> 5;
    #pragma unroll
    for (int off = 16; off >= 1; off >>= 1) s += __shfl_xor_sync(0xffffffffu, s, off);
    if (lane == 0) sm2[warp] = s;
    __syncthreads();
    float mean = (sm2[0] + sm2[1] + sm2[2] + sm2[3]) * (1.f / DM);
    float vs = 0.f;
    #pragma unroll
    for (int i = 0; i < 4; i++) { float d = v[i] - mean; vs += d * d; }
    __syncthreads();
    #pragma unroll
    for (int off = 16; off >= 1; off >>= 1) vs += __shfl_xor_sync(0xffffffffu, vs, off);
    if (lane == 0) sm2[warp] = vs;
    __syncthreads();
    float var = (sm2[0] + sm2[1] + sm2[2] + sm2[3]) * (1.f / DM);
    float inv = rsqrtf(var + 1e-5f);
    #pragma unroll
    for (int i = 0; i < 4; i++) {
        int d = tid + 128 * i;
        hr[d] = (v[i] - mean) * inv * gamma[d] + beta[d];
    }
}

// ---------------- classification head ----------------
__global__ void head_kernel(const float* __restrict__ h,
                            const float* __restrict__ Wd1, const float* __restrict__ bd1,
                            const float* __restrict__ Wd2, const float* __restrict__ bd2,
                            float* __restrict__ out)
{
    __shared__ float mid[NB][MLPD];
    int tid = threadIdx.x; // 256
    for (int b = 0; b < NB; b++) {
        const float* cls = h + (size_t)b * T * DM;
        float acc = bd1[tid];
        for (int kk = 0; kk < DM; kk++)
            acc += cls[kk] * Wd1[kk * MLPD + tid];
        mid[b][tid] = acc;
    }
    __syncthreads();
    if (tid < NB * CLASSES) {
        int b = tid / CLASSES, c = tid % CLASSES;
        float acc = bd2[c];
        for (int m = 0; m < MLPD; m++)
            acc += mid[b][m] * Wd2[m * CLASSES + c];
        out[b * CLASSES + c] = acc;
    }
}

// ---------------- GAT branch: one warp per graph ----------------
__global__ __launch_bounds__(256) void gat_kernel(
    const float* __restrict__ x, const int* __restrict__ adj,
    const float* __restrict__ Wg, const float* __restrict__ ag,
    const float* __restrict__ Wgo, const float* __restrict__ ago,
    float* __restrict__ out)
{
    int wid = threadIdx.x >> 5, lane = threadIdx.x & 31;
    int gidx = blockIdx.x * 8 + wid;
    int s = gidx / 5, g = gidx % 5;

    float xg[5][3];
    const float* xb = x + (size_t)s * NTOK + g * 3;
    #pragma unroll
    for (int n = 0; n < 5; n++)
        #pragma unroll
        for (int c = 0; c < 3; c++)
            xg[n][c] = xb[(size_t)n * SEQ * NTOK + c];

    int av = (lane < 25) ? adj[lane] : 0;
    unsigned mb = __ballot_sync(0xffffffffu, av > 0);

    float hcat[GH][5][2];
    #pragma unroll
    for (int hd = 0; hd < GH; hd++) {
        const float* W = Wg + hd * 3 * GHID;
        float w00 = W[lane],      w01 = W[GHID + lane],      w02 = W[2 * GHID + lane];
        float w10 = W[32 + lane], w11 = W[GHID + 32 + lane], w12 = W[2 * GHID + 32 + lane];
        float a1l = ag[hd * 2 * GHID + lane];
        float a1h = ag[hd * 2 * GHID + 32 + lane];
        float a2l = ag[hd * 2 * GHID + GHID + lane];
        float a2h = ag[hd * 2 * GHID + GHID + 32 + lane];
        float hv[5][2];
        #pragma unroll
        for (int n = 0; n < 5; n++) {
            hv[n][0] = xg[n][0] * w00 + xg[n][1] * w01 + xg[n][2] * w02;
            hv[n][1] = xg[n][0] * w10 + xg[n][1] * w11 + xg[n][2] * w12;
        }
        float s1[5], s2[5];
        #pragma unroll
        for (int n = 0; n < 5; n++) {
            float p1 = hv[n][0] * a1l + hv[n][1] * a1h;
            float p2 = hv[n][0] * a2l + hv[n][1] * a2h;
            #pragma unroll
            for (int off = 16; off >= 1; off >>= 1) {
                p1 += __shfl_xor_sync(0xffffffffu, p1, off);
                p2 += __shfl_xor_sync(0xffffffffu, p2, off);
            }
            s1[n] = p1; s2[n] = p2;
        }
        float att[5][5];
        #pragma unroll
        for (int i = 0; i < 5; i++) {
            float ev[5], mx = -1e30f;
            #pragma unroll
            for (int j = 0; j < 5; j++) {
                if ((mb >> (i * 5 + j)) & 1) {
                    float e = s1[i] + s2[j];
                    e = e > 0.f ? e : 0.2f * e;
                    ev[j] = e;
                    mx = fmaxf(mx, e);
                } else ev[j] = -1e30f;
            }
            float sum = 0.f;
            #pragma unroll
            for (int j = 0; j < 5; j++) {
                float p = ((mb >> (i * 5 + j)) & 1) ? __expf(ev[j] - mx) : 0.f;
                att[i][j] = p; sum += p;
            }
            float inv = 1.f / sum;
            #pragma unroll
            for (int j = 0; j < 5; j++) att[i][j] *= inv;
        }
        #pragma unroll
        for (int n = 0; n < 5; n++) {
            float o0 = 0.f, o1 = 0.f;
            #pragma unroll
            for (int j = 0; j < 5; j++) {
                o0 += att[n][j] * hv[j][0];
                o1 += att[n][j] * hv[j][1];
            }
            hcat[hd][n][0] = o0 > 0.f ? o0 : expm1f(o0);
            hcat[hd][n][1] = o1 > 0.f ? o1 : expm1f(o1);
        }
    }

    float wg0[GH][GCLS], wg1[GH][GCLS];
    #pragma unroll
    for (int hd = 0; hd < GH; hd++)
        #pragma unroll
        for (int m = 0; m < GCLS; m++) {
            wg0[hd][m] = Wgo[(hd * GHID + lane) * GCLS + m];
            wg1[hd][m] = Wgo[(hd * GHID + 32 + lane) * GCLS + m];
        }
    float h2[5][5];
    #pragma unroll
    for (int n = 0; n < 5; n++)
        #pragma unroll
        for (int m = 0; m < 5; m++) {
            float acc = 0.f;
            #pragma unroll
            for (int hd = 0; hd < GH; hd++)
                acc += hcat[hd][n][0] * wg0[hd][m] + hcat[hd][n][1] * wg1[hd][m];
            #pragma unroll
            for (int off = 16; off >= 1; off >>= 1)
                acc += __shfl_xor_sync(0xffffffffu, acc, off);
            h2[n][m] = acc;
        }

    float s1o[5], s2o[5];
    #pragma unroll
    for (int n = 0; n < 5; n++) {
        float a1 = 0.f, a2 = 0.f;
        #pragma unroll
        for (int m = 0; m < 5; m++) {
            a1 += h2[n][m] * ago[m];
            a2 += h2[n][m] * ago[GCLS + m];
        }
        s1o[n] = a1; s2o[n] = a2;
    }
    float att2[5][5];
    #pragma unroll
    for (int i = 0; i < 5; i++) {
        float ev[5], mx = -1e30f;
        #pragma unroll
        for (int j = 0; j < 5; j++) {
            if ((mb >> (i * 5 + j)) & 1) {
                float e = s1o[i] + s2o[j];
                e = e > 0.f ? e : 0.2f * e;
                ev[j] = e;
                mx = fmaxf(mx, e);
            } else ev[j] = -1e30f;
        }
        float sum = 0.f;
        #pragma unroll
        for (int j = 0; j < 5; j++) {
            float p = ((mb >> (i * 5 + j)) & 1) ? __expf(ev[j] - mx) : 0.f;
            att2[i][j] = p; sum += p;
        }
        float inv = 1.f / sum;
        #pragma unroll
        for (int j = 0; j < 5; j++) att2[i][j] *= inv;
    }
    float o2[5][5];
    #pragma unroll
    for (int n = 0; n < 5; n++)
        #pragma unroll
        for (int m = 0; m < 5; m++) {
            float o = 0.f;
            #pragma unroll
            for (int j = 0; j < 5; j++) o += att2[n][j] * h2[j][m];
            o2[n][m] = o > 0.f ? o : expm1f(o);
        }
    if (lane < 25) {
        int n = lane / 5;
        float mx = -1e30f;
        #pragma unroll
        for (int m = 0; m < 5; m++) mx = fmaxf(mx, o2[n][m]);
        float sum = 0.f;
        #pragma unroll
        for (int m = 0; m < 5; m++) sum += __expf(o2[n][m] - mx);
        float lse = mx + logf(sum);
        out[OUT_GAT_BASE + (size_t)gidx * 25 + lane] = o2[n][lane % 5] - lse;
    }
}

// ---------------- host orchestration ----------------
extern "C" void kernel_launch(void* const* d_in, const int* in_sizes, int n_in,
                              void* d_out, int out_size)
{
    const float* x       = (const float*)d_in[0];
    const int*   adj     = (const int*)  d_in[1];
    const float* W_enc   = (const float*)d_in[2];
    const float* b_enc   = (const float*)d_in[3];
    const float* cls_tok = (const float*)d_in[4];
    const float* pos_emb = (const float*)d_in[5];
    const float* Wq      = (const float*)d_in[6];
    const float* bq      = (const float*)d_in[7];
    const float* Wk      = (const float*)d_in[8];
    const float* bk      = (const float*)d_in[9];
    const float* Wv      = (const float*)d_in[10];
    const float* bv      = (const float*)d_in[11];
    const float* Wo      = (const float*)d_in[12];
    const float* bo      = (const float*)d_in[13];
    const float* W1      = (const float*)d_in[14];
    const float* b1      = (const float*)d_in[15];
    const float* W2      = (const float*)d_in[16];
    const float* b2      = (const float*)d_in[17];
    const float* g1      = (const float*)d_in[18];
    const float* be1     = (const float*)d_in[19];
    const float* g2      = (const float*)d_in[20];
    const float* be2     = (const float*)d_in[21];
    const float* Wd1     = (const float*)d_in[22];
    const float* bd1     = (const float*)d_in[23];
    const float* Wd2     = (const float*)d_in[24];
    const float* bd2     = (const float*)d_in[25];
    const float* Wg      = (const float*)d_in[26];
    const float* ag      = (const float*)d_in[27];
    const float* Wgo     = (const float*)d_in[28];
    const float* ago     = (const float*)d_in[29];
    float* out = (float*)d_out;

    float *h, *q, *k, *v, *ao, *t, *ff;
    float *WqF, *WkF, *WvF, *WoF, *W1F, *W2F;
    cudaGetSymbolAddress((void**)&h,   g_h);
    cudaGetSymbolAddress((void**)&q,   g_q);
    cudaGetSymbolAddress((void**)&k,   g_k);
    cudaGetSymbolAddress((void**)&v,   g_v);
    cudaGetSymbolAddress((void**)&ao,  g_ao);
    cudaGetSymbolAddress((void**)&t,   g_t);
    cudaGetSymbolAddress((void**)&ff,  g_ff);
    cudaGetSymbolAddress((void**)&WqF, g_WqF);
    cudaGetSymbolAddress((void**)&WkF, g_WkF);
    cudaGetSymbolAddress((void**)&WvF, g_WvF);
    cudaGetSymbolAddress((void**)&WoF, g_WoF);
    cudaGetSymbolAddress((void**)&W1F, g_W1F);
    cudaGetSymbolAddress((void**)&W2F, g_W2F);

    cudaFuncSetAttribute(mma_gemm, cudaFuncAttributeMaxDynamicSharedMemorySize, MM_SMEM);
    cudaFuncSetAttribute(mma_gemm_qkv, cudaFuncAttributeMaxDynamicSharedMemorySize, MM_SMEM);
    cudaFuncSetAttribute(attn_mma_kernel, cudaFuncAttributeMaxDynamicSharedMemorySize, ATT_SMEM);

    // all weight fragment-packs (tf32-rounded) in one launch
    frag_all<<<12288, 256>>>(Wq, Wk, Wv, Wo, W1, W2, WqF, WkF, WvF, WoF, W1F, W2F);

    gat_kernel<<<GAT_GRAPHS / 8, 256>>>(x, adj, Wg, ag, Wgo, ago, out);
    enc_kernel<<<MROWS, 128>>>(x, W_enc, b_enc, cls_tok, pos_emb, h);

    int gy = (MROWS + 127) / 128;    // 41
    dim3 grid_qkv(DM / 128, gy, 3);
    dim3 grid_dm(DM / 128, gy);
    dim3 grid_ff(DFF / 128, gy);
    dim3 attn_grid((T + 127) / 128, NHEAD, NB);   // 9 x 8 x 5

    for (int l = 0; l < NL; l++) {
        mma_gemm_qkv<<<grid_qkv, 256, MM_SMEM>>>(
            h, WqF + (size_t)l * DM * DM, WkF + (size_t)l * DM * DM, WvF + (size_t)l * DM * DM,
            bq + l * DM, bk + l * DM, bv + l * DM, q, k, v);
        attn_mma_kernel<<<attn_grid, 256, ATT_SMEM>>>(q, k, v, ao);
        mma_gemm<<<grid_dm, 256, MM_SMEM>>>(ao, WoF + (size_t)l * DM * DM, bo + l * DM, t, MROWS, DM, DM, 0);
        add_ln_kernel<<<MROWS, 128>>>(h, t, g1 + l * DM, be1 + l * DM);
        mma_gemm<<<grid_ff, 256, MM_SMEM>>>(h, W1F + (size_t)l * DM * DFF, b1 + l * DFF, ff, MROWS, DFF, DM, 1);
        mma_gemm<<<grid_dm, 256, MM_SMEM>>>(ff, W2F + (size_t)l * DFF * DM, b2 + l * DM, t, MROWS, DM, DFF, 0);
        add_ln_kernel<<<MROWS, 128>>>(h, t, g2 + l * DM, be2 + l * DM);
    }

    head_kernel<<<1, 256>>>(h, Wd1, bd1, Wd2, bd2, out);
}